// round 13
// baseline (speedup 1.0000x reference)
#include <cuda_runtime.h>
#include <math.h>

#define NB 8
#define NH 1024
#define NW 1024
#define HW (1 << 20)
#define BHW (NB * HW)

#define NU 0.01f
#define DT 0.01f

#define PD(i) ((i) + ((i) >> 5))

#define C1ROW 520                      // compact spectral row stride (slots 0..512 used, natural kx)
#define C1BATCH (1024 * C1ROW)

// ------------------------- device scratch -------------------------
__device__ float  g_fa[2 * BHW];
__device__ float  g_unew[BHW];
__device__ float  g_vnew[BHW];
__device__ float2 g_c1[NB * C1BATCH];
__device__ float  g_pcorr[BHW];
__device__ float  g_partials[16384];
__device__ float  g_invnorm[16];
__device__ unsigned int g_counter = 0;

// ------------------------- complex helpers -------------------------
__device__ __forceinline__ float2 cmul(float2 a, float2 b) {
    return make_float2(a.x * b.x - a.y * b.y, a.x * b.y + a.y * b.x);
}
__device__ __forceinline__ float2 cadd(float2 a, float2 b) { return make_float2(a.x + b.x, a.y + b.y); }
__device__ __forceinline__ float2 csub(float2 a, float2 b) { return make_float2(a.x - b.x, a.y - b.y); }

__device__ __forceinline__ constexpr int brev5(int v) {
    return ((v & 1) << 4) | ((v & 2) << 2) | (v & 4) | ((v & 8) >> 2) | ((v & 16) >> 4);
}
__device__ __forceinline__ int brev10(int v) { return (int)(__brev((unsigned)v) >> 22); }

// W_32^q = exp(-2*pi*i*q/32), q=0..15
__constant__ float2 W32C[16] = {
    { 1.000000000f, -0.000000000f}, { 0.980785280f, -0.195090322f},
    { 0.923879533f, -0.382683432f}, { 0.831469612f, -0.555570233f},
    { 0.707106781f, -0.707106781f}, { 0.555570233f, -0.831469612f},
    { 0.382683432f, -0.923879533f}, { 0.195090322f, -0.980785280f},
    { 0.000000000f, -1.000000000f}, {-0.195090322f, -0.980785280f},
    {-0.382683432f, -0.923879533f}, {-0.555570233f, -0.831469612f},
    {-0.707106781f, -0.707106781f}, {-0.831469612f, -0.555570233f},
    {-0.923879533f, -0.382683432f}, {-0.980785280f, -0.195090322f},
};

// 32-pt in-place DIF (natural in, X[k] at r[brev5(k)])
__device__ __forceinline__ void dif32(float2* r) {
    #pragma unroll
    for (int t = 0; t < 5; t++) {
        const int h = 16 >> t;
        #pragma unroll
        for (int g = 0; g < (16 / h); g++) {
            #pragma unroll
            for (int q = 0; q < h; q++) {
                int i0 = ((g * h) << 1) + q, i1 = i0 + h;
                float2 A = r[i0], B = r[i1];
                r[i0] = cadd(A, B);
                r[i1] = cmul(csub(A, B), W32C[q << t]);
            }
        }
    }
}

// Warp 1024-pt forward FFT. In: r[n1] = z[32*n1 + lane]. Out: r[j] = Z[32*brev5(j) + lane].
__device__ __forceinline__ void fft1024_warp(float2* r, float2* zb, int lane) {
    dif32(r);
    float sn, cs;
    sincosf((float)lane * -6.135923151542565e-3f, &sn, &cs);   // -2*pi*lane/1024
    float2 w1 = make_float2(cs, sn), w = w1;
    #pragma unroll
    for (int k1 = 1; k1 < 32; k1++) {
        r[brev5(k1)] = cmul(r[brev5(k1)], w);
        w = cmul(w, w1);
    }
    __syncwarp();
    #pragma unroll
    for (int k1 = 0; k1 < 32; k1++) zb[lane * 33 + k1] = r[brev5(k1)];
    __syncwarp();
    #pragma unroll
    for (int n2 = 0; n2 < 32; n2++) r[n2] = zb[n2 * 33 + lane];
    dif32(r);
}

// ------------------------- block radix-4 machinery -------------------------
__device__ __forceinline__ void build_tw(float* twR, float* twI, int tid) {
    #pragma unroll
    for (int k = 0; k < 2; k++) {
        int j = tid + k * 256;
        float sn, cs;
        sincosf(-6.283185307179586f * (float)j * (1.0f / 1024.0f), &sn, &cs);
        twR[PD(j)] = cs; twI[PD(j)] = sn;
    }
}

#define FWD_DOUBLE(sR, sI, twR, twI, bi, t)                                     \
{                                                                               \
    const int h = 512 >> (t), h2 = h >> 1;                                      \
    int q = (bi) & (h2 - 1);                                                    \
    int B = (bi) >> (8 - (t));                                                  \
    int adr = B * (h << 1) + q;                                                 \
    int a0 = PD(adr), a1 = PD(adr + h2), a2 = PD(adr + h), a3 = PD(adr + h + h2); \
    float x0r = sR[a0], x0i = sI[a0], x1r = sR[a1], x1i = sI[a1];               \
    float x2r = sR[a2], x2i = sI[a2], x3r = sR[a3], x3i = sI[a3];               \
    int i0 = PD(q << (t)), i1 = PD(q << ((t) + 1));                             \
    float w0r = twR[i0], w0i = twI[i0];                                         \
    float w1r = twR[i1], w1i = twI[i1];                                         \
    float u0r = x0r + x2r, u0i = x0i + x2i;                                     \
    float d0r = x0r - x2r, d0i = x0i - x2i;                                     \
    float e0r = d0r * w0r - d0i * w0i, e0i = d0r * w0i + d0i * w0r;             \
    float u1r = x1r + x3r, u1i = x1i + x3i;                                     \
    float d1r = x1r - x3r, d1i = x1i - x3i;                                     \
    float e1r = d1r * w0i + d1i * w0r, e1i = -d1r * w0r + d1i * w0i;            \
    sR[a0] = u0r + u1r; sI[a0] = u0i + u1i;                                     \
    float f0r = u0r - u1r, f0i = u0i - u1i;                                     \
    sR[a1] = f0r * w1r - f0i * w1i; sI[a1] = f0r * w1i + f0i * w1r;             \
    sR[a2] = e0r + e1r; sI[a2] = e0i + e1i;                                     \
    float f1r = e0r - e1r, f1i = e0i - e1i;                                     \
    sR[a3] = f1r * w1r - f1i * w1i; sI[a3] = f1r * w1i + f1i * w1r;             \
}

#define INV_DOUBLE(sR, sI, twR, twI, bi, t)                                     \
{                                                                               \
    const int h = 1 << (t);                                                     \
    int q = (bi) & (h - 1);                                                     \
    int B = (bi) >> (t);                                                        \
    int e0 = B * (h << 2) + q;                                                  \
    int a0 = PD(e0), a1 = PD(e0 + h), a2 = PD(e0 + 2 * h), a3 = PD(e0 + 3 * h); \
    float x0r = sR[a0], x0i = sI[a0], x1r = sR[a1], x1i = sI[a1];               \
    float x2r = sR[a2], x2i = sI[a2], x3r = sR[a3], x3i = sI[a3];               \
    int i0 = PD(q << (9 - (t))), i1 = PD(q << (8 - (t)));                       \
    float c0r = twR[i0], c0i = -twI[i0];                                        \
    float c1r = twR[i1], c1i = -twI[i1];                                        \
    float t1r = c0r * x1r - c0i * x1i, t1i = c0r * x1i + c0i * x1r;             \
    float b0r = x0r + t1r, b0i = x0i + t1i, b1r = x0r - t1r, b1i = x0i - t1i;   \
    float t3r = c0r * x3r - c0i * x3i, t3i = c0r * x3i + c0i * x3r;             \
    float b2r = x2r + t3r, b2i = x2i + t3i, b3r = x2r - t3r, b3i = x2i - t3i;   \
    float t2r = c1r * b2r - c1i * b2i, t2i = c1r * b2i + c1i * b2r;             \
    sR[a0] = b0r + t2r; sI[a0] = b0i + t2i;                                     \
    sR[a2] = b0r - t2r; sI[a2] = b0i - t2i;                                     \
    float gr = -c1i, gi = c1r;                                                  \
    float t4r = gr * b3r - gi * b3i, t4i = gr * b3i + gi * b3r;                 \
    sR[a1] = b1r + t4r; sI[a1] = b1i + t4i;                                     \
    sR[a3] = b1r - t4r; sI[a3] = b1i - t4i;                                     \
}

// ------------------------- block reduce -------------------------
__device__ __forceinline__ float block_reduce_256(float v, float* red) {
    #pragma unroll
    for (int o = 16; o > 0; o >>= 1) v += __shfl_down_sync(0xffffffffu, v, o);
    int lane = threadIdx.x & 31, wid = threadIdx.x >> 5;
    if (lane == 0) red[wid] = v;
    __syncthreads();
    float s = 0.0f;
    if (wid == 0) {
        s = (lane < 8) ? red[lane] : 0.0f;
        #pragma unroll
        for (int o = 4; o > 0; o >>= 1) s += __shfl_down_sync(0xffffffffu, s, o);
    }
    return s;
}

// ------------------------- fused 3x smoothing + norm partials + last-block finalize -------------------------
__global__ void smooth3_kernel(const float* __restrict__ su_ext,
                               const float* __restrict__ sv_ext) {
    __shared__ float t0[38][40];
    __shared__ float t1[38][40];
    __shared__ float red[8];
    __shared__ bool isLast;
    int slab = blockIdx.y;
    int fb = slab >> 3, b = slab & 7;
    const float* src = (fb ? sv_ext : su_ext) + (b << 20);
    int tile = blockIdx.x;
    int ty0 = (tile >> 5) << 5;
    int tx0 = (tile & 31) << 5;
    int tid = threadIdx.x;

    for (int i = tid; i < 38 * 38; i += 256) {
        int ly = i / 38, lx = i - ly * 38;
        int gy = (ty0 + ly - 3) & 1023;
        int gx = (tx0 + lx - 3) & 1023;
        t0[ly][lx] = src[(gy << 10) + gx];
    }
    __syncthreads();
    for (int i = tid; i < 36 * 36; i += 256) {
        int ly = i / 36, lx = i - ly * 36;
        ly += 1; lx += 1;
        float c = t0[ly][lx];
        t1[ly][lx] = c + 0.1f * (t0[ly][lx-1] + t0[ly][lx+1] + t0[ly-1][lx] + t0[ly+1][lx] - 4.0f * c);
    }
    __syncthreads();
    for (int i = tid; i < 34 * 34; i += 256) {
        int ly = i / 34, lx = i - ly * 34;
        ly += 2; lx += 2;
        float c = t1[ly][lx];
        t0[ly][lx] = c + 0.1f * (t1[ly][lx-1] + t1[ly][lx+1] + t1[ly-1][lx] + t1[ly+1][lx] - 4.0f * c);
    }
    __syncthreads();
    float ss = 0.0f;
    float* dst = g_fa + fb * BHW + (b << 20);
    for (int i = tid; i < 1024; i += 256) {
        int ly = (i >> 5) + 3, lx = (i & 31) + 3;
        float c = t0[ly][lx];
        float o = c + 0.1f * (t0[ly][lx-1] + t0[ly][lx+1] + t0[ly-1][lx] + t0[ly+1][lx] - 4.0f * c);
        dst[((ty0 + ly - 3) << 10) + (tx0 + lx - 3)] = o;
        ss += o * o;
    }
    float tot = block_reduce_256(ss, red);
    if (tid == 0) {
        g_partials[slab * 1024 + tile] = tot;
        __threadfence();
        unsigned int old = atomicInc(&g_counter, 0xFFFFFFFFu);
        isLast = (old == 16383u);
    }
    __syncthreads();

    if (isLast) {
        // deterministic final reduction for all 16 slabs (single block, fixed order)
        #pragma unroll 1
        for (int r = 0; r < 16; r++) {
            float s = 0.0f;
            for (int i = tid; i < 1024; i += 256) s += g_partials[r * 1024 + i];
            __syncthreads();
            float tt = block_reduce_256(s, red);
            if (tid == 0) {
                float nrm = sqrtf(tt);
                g_invnorm[r] = 1.0f / fmaxf(nrm, 1e-12f);
            }
            __syncthreads();
        }
        if (tid == 0) g_counter = 0;      // reset for next graph replay
    }
}

// ------------------------- main update (float4 vectorized) -------------------------
__global__ void update_kernel(const float* __restrict__ xin,
                              const float* __restrict__ beta) {
    int gid = blockIdx.x * 256 + threadIdx.x;          // over BHW/4
    int b  = gid >> 18;
    int t  = gid & 0x3FFFF;
    int y  = t >> 8;
    int x4 = (t & 255) << 2;
    int row = y << 10;
    int rp = ((y + 1) & 1023) << 10;
    int rm = ((y - 1) & 1023) << 10;
    int xm = (x4 - 1) & 1023, xp = (x4 + 4) & 1023;

    const float* u = xin + (size_t)(b * 3 + 0) * HW;
    const float* v = xin + (size_t)(b * 3 + 1) * HW;
    const float* p = xin + (size_t)(b * 3 + 2) * HW;

    float4 uc4  = *(const float4*)(u + row + x4);
    float4 uyp4 = *(const float4*)(u + rp + x4);
    float4 uym4 = *(const float4*)(u + rm + x4);
    float  uml  = u[row + xm], upr = u[row + xp];

    float4 vc4  = *(const float4*)(v + row + x4);
    float4 vyp4 = *(const float4*)(v + rp + x4);
    float4 vym4 = *(const float4*)(v + rm + x4);
    float  vml  = v[row + xm], vpr = v[row + xp];

    float4 pc4  = *(const float4*)(p + row + x4);
    float4 pyp4 = *(const float4*)(p + rp + x4);
    float4 pym4 = *(const float4*)(p + rm + x4);
    float  pml  = p[row + xm], ppr = p[row + xp];

    float4 fu4 = *(const float4*)(g_fa + (b << 20) + row + x4);
    float4 fv4 = *(const float4*)(g_fa + BHW + (b << 20) + row + x4);

    float sb = sqrtf(beta[b]);
    float inu = g_invnorm[b], inv_ = g_invnorm[8 + b];

    float uu[6] = {uml, uc4.x, uc4.y, uc4.z, uc4.w, upr};
    float vv[6] = {vml, vc4.x, vc4.y, vc4.z, vc4.w, vpr};
    float pp[6] = {pml, pc4.x, pc4.y, pc4.z, pc4.w, ppr};
    float uypA[4] = {uyp4.x, uyp4.y, uyp4.z, uyp4.w};
    float uymA[4] = {uym4.x, uym4.y, uym4.z, uym4.w};
    float vypA[4] = {vyp4.x, vyp4.y, vyp4.z, vyp4.w};
    float vymA[4] = {vym4.x, vym4.y, vym4.z, vym4.w};
    float pypA[4] = {pyp4.x, pyp4.y, pyp4.z, pyp4.w};
    float pymA[4] = {pym4.x, pym4.y, pym4.z, pym4.w};
    float fuA[4]  = {fu4.x, fu4.y, fu4.z, fu4.w};
    float fvA[4]  = {fv4.x, fv4.y, fv4.z, fv4.w};

    float uo[4], vo[4];
    #pragma unroll
    for (int i = 0; i < 4; i++) {
        float uc = uu[i + 1], vc = vv[i + 1];
        float adv_u = uc * 0.5f * (uu[i + 2] - uu[i]) + vc * 0.5f * (uypA[i] - uymA[i]);
        float adv_v = uc * 0.5f * (vv[i + 2] - vv[i]) + vc * 0.5f * (vypA[i] - vymA[i]);
        float lap_u = uu[i + 2] + uu[i] + uypA[i] + uymA[i] - 4.0f * uc;
        float lap_v = vv[i + 2] + vv[i] + vypA[i] + vymA[i] - 4.0f * vc;
        float dpdx = 0.5f * (pp[i + 2] - pp[i]);
        float dpdy = 0.5f * (pypA[i] - pymA[i]);
        uo[i] = uc + DT * (-adv_u + NU * lap_u - dpdx) + sb * (fuA[i] * inu);
        vo[i] = vc + DT * (-adv_v + NU * lap_v - dpdy) + sb * (fvA[i] * inv_);
    }
    *(float4*)(g_unew + (b << 20) + row + x4) = make_float4(uo[0], uo[1], uo[2], uo[3]);
    *(float4*)(g_vnew + (b << 20) + row + x4) = make_float4(vo[0], vo[1], vo[2], vo[3]);
}

// ------------------------- fwd FFT over x: one warp per packed row pair -------------------------
__global__ void __launch_bounds__(128) fft_fwd_div_kernel() {
    __shared__ float2 pool[4 * 1056];
    int tid = threadIdx.x, wid = tid >> 5, lane = tid & 31;
    int pairId = blockIdx.x * 4 + wid;       // b*512 + yp
    int b = pairId >> 9, yp = pairId & 511;
    int y0 = yp << 1, y1 = y0 + 1;
    int ub = b << 20;
    int r0 = y0 << 10, r1 = y1 << 10;
    int ym0 = ((y0 - 1) & 1023) << 10;
    int yp1 = ((y1 + 1) & 1023) << 10;

    float2 r[32];
    #pragma unroll
    for (int n1 = 0; n1 < 32; n1++) {
        int x = (n1 << 5) + lane;
        int xp = (x + 1) & 1023, xm = (x - 1) & 1023;
        float d0 = 0.5f * (g_unew[ub + r0 + xp] - g_unew[ub + r0 + xm])
                 + 0.5f * (g_vnew[ub + r1 + x]  - g_vnew[ub + ym0 + x]);
        float d1 = 0.5f * (g_unew[ub + r1 + xp] - g_unew[ub + r1 + xm])
                 + 0.5f * (g_vnew[ub + yp1 + x] - g_vnew[ub + r0 + x]);
        r[n1] = make_float2(d0, d1);
    }

    float2* zb = pool + wid * 1056;
    fft1024_warp(r, zb, lane);

    __syncwarp();
    #pragma unroll
    for (int k2 = 0; k2 < 32; k2++) zb[k2 * 33 + lane] = r[brev5(k2)];
    __syncwarp();

    float2* c0 = g_c1 + b * C1BATCH + y0 * C1ROW;
    float2* c1 = g_c1 + b * C1BATCH + y1 * C1ROW;
    #pragma unroll
    for (int m = 0; m < 17; m++) {
        int k = lane + (m << 5);
        if (k <= 512) {
            int km = (1024 - k) & 1023;
            float2 A = zb[(k >> 5) * 33 + (k & 31)];
            float2 B = zb[(km >> 5) * 33 + (km & 31)];
            c0[k] = make_float2(0.5f * (A.x + B.x), 0.5f * (A.y - B.y));
            c1[k] = make_float2(0.5f * (A.y + B.y), 0.5f * (B.x - A.x));
        }
    }
}

// ------------------------- fused column pipeline (block radix-4, natural kx) -------------------------
#define CS 1057
__global__ void fft_col_poisson_kernel() {
    __shared__ float sR[4 * CS], sI[4 * CS];
    __shared__ float twR[528], twI[528];

    int blk = blockIdx.x;                    // b*129 + g
    int b = blk / 129, g = blk - b * 129;
    int col0 = g << 2;
    int tid = threadIdx.x;                   // 256
    float2* base = g_c1 + b * C1BATCH;

    build_tw(twR, twI, tid);

    int c = tid & 3, yy = tid >> 2;
    int col = col0 + c;                      // natural spectral kx (valid cols <= 512; pad cols harmless)
    #pragma unroll
    for (int m = 0; m < 16; m++) {
        int y = yy + (m << 6);
        float2 v = base[y * C1ROW + col];
        sR[c * CS + PD(y)] = v.x; sI[c * CS + PD(y)] = v.y;
    }
    __syncthreads();

    int cc = tid >> 6, r = tid & 63;
    float* cR = sR + cc * CS;
    float* cI = sI + cc * CS;

    #pragma unroll
    for (int t = 0; t < 10; t += 2) {
        #pragma unroll
        for (int k = 0; k < 4; k++) {
            int bi = r + (k << 6);
            FWD_DOUBLE(cR, cI, twR, twI, bi, t);
        }
        __syncthreads();
    }

    // Poisson multiplier: y index bit-reversed (DIF output), kx natural
    float tkx = (float)min(col, 512);
    #pragma unroll
    for (int m = 0; m < 16; m++) {
        int ry = yy + (m << 6);
        int ky = brev10(ry);
        float tky = (float)min(ky, 1024 - ky);
        float k2 = tkx * tkx + tky * tky;
        float mm = (col == 0 && ky == 0) ? 0.0f
                 : (-1.0f / (39.47841760435743f * k2)) * (1.0f / 1024.0f);
        int a = c * CS + PD(ry);
        sR[a] *= mm; sI[a] *= mm;
    }
    __syncthreads();

    #pragma unroll
    for (int t = 0; t < 10; t += 2) {
        #pragma unroll
        for (int k = 0; k < 4; k++) {
            int bi = r + (k << 6);
            INV_DOUBLE(cR, cI, twR, twI, bi, t);
        }
        __syncthreads();
    }

    #pragma unroll
    for (int m = 0; m < 16; m++) {
        int y = yy + (m << 6);
        base[y * C1ROW + col] = make_float2(sR[c * CS + PD(y)], sI[c * CS + PD(y)]);
    }
}

// ------------------------- inverse FFT over x (block radix-4, PD-padded spectra stage) -------------------------
__global__ void fft_inv_real_kernel() {
    __shared__ float sR[1056], sI[1056];
    __shared__ float twR[528], twI[528];
    __shared__ float a1R[536], a1I[536], a2R[536], a2I[536];   // PD-padded (max PD(512)=528)

    int blk = blockIdx.x;                    // b*512 + yp
    int b = blk >> 9, yp = blk & 511;
    int y0 = yp << 1, y1 = y0 + 1;
    int tid = threadIdx.x;                   // 256

    build_tw(twR, twI, tid);
    const float2* c0 = g_c1 + b * C1BATCH + y0 * C1ROW;
    const float2* c1 = g_c1 + b * C1BATCH + y1 * C1ROW;
    #pragma unroll
    for (int k = 0; k < 2; k++) {
        int cc = tid + k * 256;
        float2 v1 = c0[cc], v2 = c1[cc];
        a1R[PD(cc)] = v1.x; a1I[PD(cc)] = v1.y;
        a2R[PD(cc)] = v2.x; a2I[PD(cc)] = v2.y;
    }
    if (tid == 0) {
        float2 v1 = c0[512], v2 = c1[512];
        a1R[PD(512)] = v1.x; a1I[PD(512)] = v1.y;
        a2R[PD(512)] = v2.x; a2I[PD(512)] = v2.y;
    }
    __syncthreads();

    // build packed spectrum B = S1 + i*S2 at DIF-bitrev storage position j (spectral k = brev(j))
    #pragma unroll
    for (int k = 0; k < 4; k++) {
        int j = tid + k * 256;
        int kk = brev10(j);
        float br, bi;
        if (kk <= 512) {
            int a = PD(kk);
            br = a1R[a] - a2I[a];
            bi = a1I[a] + a2R[a];
        } else {
            int a = PD(1024 - kk);
            br = a1R[a] + a2I[a];
            bi = -a1I[a] + a2R[a];
        }
        sR[PD(j)] = br; sI[PD(j)] = bi;
    }
    __syncthreads();

    #pragma unroll
    for (int t = 0; t < 10; t += 2) {
        INV_DOUBLE(sR, sI, twR, twI, tid, t);
        __syncthreads();
    }

    const float sc = 1.0f / 1024.0f;
    int bb = b << 20;
    #pragma unroll
    for (int k = 0; k < 4; k++) {
        int x = tid + k * 256;
        g_pcorr[bb + (y0 << 10) + x] = sR[PD(x)] * sc;
        g_pcorr[bb + (y1 << 10) + x] = sI[PD(x)] * sc;
    }
}

// ------------------------- final (float4 vectorized): subtract grad(p_corr), stack output -------------------------
__global__ void final_kernel(const float* __restrict__ xin, float* __restrict__ out) {
    int gid = blockIdx.x * 256 + threadIdx.x;          // over BHW/4
    int b  = gid >> 18;
    int t  = gid & 0x3FFFF;
    int y  = t >> 8;
    int x4 = (t & 255) << 2;
    int row = y << 10;
    int rp = ((y + 1) & 1023) << 10;
    int rm = ((y - 1) & 1023) << 10;
    int xm = (x4 - 1) & 1023, xp = (x4 + 4) & 1023;
    int bb = b << 20;

    const float* pc = g_pcorr + bb;
    float4 pcc4 = *(const float4*)(pc + row + x4);
    float4 pyp4 = *(const float4*)(pc + rp + x4);
    float4 pym4 = *(const float4*)(pc + rm + x4);
    float  pml  = pc[row + xm], ppr = pc[row + xp];

    float4 un4 = *(const float4*)(g_unew + bb + row + x4);
    float4 vn4 = *(const float4*)(g_vnew + bb + row + x4);
    float4 pin4 = *(const float4*)(xin + (size_t)(b * 3 + 2) * HW + row + x4);

    float ppx[6] = {pml, pcc4.x, pcc4.y, pcc4.z, pcc4.w, ppr};
    float pypA[4] = {pyp4.x, pyp4.y, pyp4.z, pyp4.w};
    float pymA[4] = {pym4.x, pym4.y, pym4.z, pym4.w};
    float unA[4] = {un4.x, un4.y, un4.z, un4.w};
    float vnA[4] = {vn4.x, vn4.y, vn4.z, vn4.w};
    float pinA[4] = {pin4.x, pin4.y, pin4.z, pin4.w};

    float uo[4], vo[4], po[4];
    #pragma unroll
    for (int i = 0; i < 4; i++) {
        uo[i] = unA[i] - 0.5f * (ppx[i + 2] - ppx[i]);
        vo[i] = vnA[i] - 0.5f * (pypA[i] - pymA[i]);
        po[i] = pinA[i] + ppx[i + 1];
    }
    *(float4*)(out + (size_t)(b * 3 + 0) * HW + row + x4) = make_float4(uo[0], uo[1], uo[2], uo[3]);
    *(float4*)(out + (size_t)(b * 3 + 1) * HW + row + x4) = make_float4(vo[0], vo[1], vo[2], vo[3]);
    *(float4*)(out + (size_t)(b * 3 + 2) * HW + row + x4) = make_float4(po[0], po[1], po[2], po[3]);
}

// ------------------------- launch -------------------------
extern "C" void kernel_launch(void* const* d_in, const int* in_sizes, int n_in,
                              void* d_out, int out_size) {
    (void)in_sizes; (void)n_in; (void)out_size;
    const float* x    = (const float*)d_in[0];
    const float* beta = (const float*)d_in[1];
    const float* fu   = (const float*)d_in[2];
    const float* fv   = (const float*)d_in[3];
    float* out = (float*)d_out;

    smooth3_kernel<<<dim3(1024, 16), 256>>>(fu, fv);
    update_kernel<<<BHW / 4 / 256, 256>>>(x, beta);
    fft_fwd_div_kernel<<<1024, 128>>>();
    fft_col_poisson_kernel<<<NB * 129, 256>>>();
    fft_inv_real_kernel<<<NB * 512, 256>>>();
    final_kernel<<<BHW / 4 / 256, 256>>>(x, out);
}

// round 14
// speedup vs baseline: 1.0626x; 1.0626x over previous
#include <cuda_runtime.h>
#include <math.h>

#define NB 8
#define NH 1024
#define NW 1024
#define HW (1 << 20)
#define BHW (NB * HW)

#define NU 0.01f
#define DT 0.01f

#define PD(i) ((i) + ((i) >> 5))

#define C1ROW 520                      // compact spectral row stride (slots 0..512 used, natural kx)
#define C1BATCH (1024 * C1ROW)

// ------------------------- device scratch -------------------------
__device__ float  g_fa[2 * BHW];
__device__ float  g_unew[BHW];
__device__ float  g_vnew[BHW];
__device__ float2 g_c1[NB * C1BATCH];
__device__ float  g_pcorr[BHW];
__device__ float  g_partials[16384];
__device__ float  g_invnorm[16];

// ------------------------- complex helpers -------------------------
__device__ __forceinline__ float2 cmul(float2 a, float2 b) {
    return make_float2(a.x * b.x - a.y * b.y, a.x * b.y + a.y * b.x);
}
__device__ __forceinline__ float2 cadd(float2 a, float2 b) { return make_float2(a.x + b.x, a.y + b.y); }
__device__ __forceinline__ float2 csub(float2 a, float2 b) { return make_float2(a.x - b.x, a.y - b.y); }

__device__ __forceinline__ constexpr int brev5(int v) {
    return ((v & 1) << 4) | ((v & 2) << 2) | (v & 4) | ((v & 8) >> 2) | ((v & 16) >> 4);
}
__device__ __forceinline__ int brev10(int v) { return (int)(__brev((unsigned)v) >> 22); }

// W_32^q = exp(-2*pi*i*q/32), q=0..15
__constant__ float2 W32C[16] = {
    { 1.000000000f, -0.000000000f}, { 0.980785280f, -0.195090322f},
    { 0.923879533f, -0.382683432f}, { 0.831469612f, -0.555570233f},
    { 0.707106781f, -0.707106781f}, { 0.555570233f, -0.831469612f},
    { 0.382683432f, -0.923879533f}, { 0.195090322f, -0.980785280f},
    { 0.000000000f, -1.000000000f}, {-0.195090322f, -0.980785280f},
    {-0.382683432f, -0.923879533f}, {-0.555570233f, -0.831469612f},
    {-0.707106781f, -0.707106781f}, {-0.831469612f, -0.555570233f},
    {-0.923879533f, -0.382683432f}, {-0.980785280f, -0.195090322f},
};

// 32-pt in-place DIF (natural in, X[k] at r[brev5(k)])
__device__ __forceinline__ void dif32(float2* r) {
    #pragma unroll
    for (int t = 0; t < 5; t++) {
        const int h = 16 >> t;
        #pragma unroll
        for (int g = 0; g < (16 / h); g++) {
            #pragma unroll
            for (int q = 0; q < h; q++) {
                int i0 = ((g * h) << 1) + q, i1 = i0 + h;
                float2 A = r[i0], B = r[i1];
                r[i0] = cadd(A, B);
                r[i1] = cmul(csub(A, B), W32C[q << t]);
            }
        }
    }
}

// Warp 1024-pt forward FFT. In: r[n1] = z[32*n1 + lane]. Out: r[j] = Z[32*brev5(j) + lane].
__device__ __forceinline__ void fft1024_warp(float2* r, float2* zb, int lane) {
    dif32(r);
    float sn, cs;
    __sincosf((float)lane * -6.135923151542565e-3f, &sn, &cs);   // -2*pi*lane/1024
    float2 w1 = make_float2(cs, sn), w = w1;
    #pragma unroll
    for (int k1 = 1; k1 < 32; k1++) {
        r[brev5(k1)] = cmul(r[brev5(k1)], w);
        w = cmul(w, w1);
    }
    __syncwarp();
    #pragma unroll
    for (int k1 = 0; k1 < 32; k1++) zb[lane * 33 + k1] = r[brev5(k1)];
    __syncwarp();
    #pragma unroll
    for (int n2 = 0; n2 < 32; n2++) r[n2] = zb[n2 * 33 + lane];
    dif32(r);
}

// ------------------------- block radix-4 machinery -------------------------
__device__ __forceinline__ void build_tw(float* twR, float* twI, int tid) {
    #pragma unroll
    for (int k = 0; k < 2; k++) {
        int j = tid + k * 256;
        float sn, cs;
        __sincosf(-6.283185307179586f * (float)j * (1.0f / 1024.0f), &sn, &cs);
        twR[PD(j)] = cs; twI[PD(j)] = sn;
    }
}

#define FWD_DOUBLE(sR, sI, twR, twI, bi, t)                                     \
{                                                                               \
    const int h = 512 >> (t), h2 = h >> 1;                                      \
    int q = (bi) & (h2 - 1);                                                    \
    int B = (bi) >> (8 - (t));                                                  \
    int adr = B * (h << 1) + q;                                                 \
    int a0 = PD(adr), a1 = PD(adr + h2), a2 = PD(adr + h), a3 = PD(adr + h + h2); \
    float x0r = sR[a0], x0i = sI[a0], x1r = sR[a1], x1i = sI[a1];               \
    float x2r = sR[a2], x2i = sI[a2], x3r = sR[a3], x3i = sI[a3];               \
    int i0 = PD(q << (t)), i1 = PD(q << ((t) + 1));                             \
    float w0r = twR[i0], w0i = twI[i0];                                         \
    float w1r = twR[i1], w1i = twI[i1];                                         \
    float u0r = x0r + x2r, u0i = x0i + x2i;                                     \
    float d0r = x0r - x2r, d0i = x0i - x2i;                                     \
    float e0r = d0r * w0r - d0i * w0i, e0i = d0r * w0i + d0i * w0r;             \
    float u1r = x1r + x3r, u1i = x1i + x3i;                                     \
    float d1r = x1r - x3r, d1i = x1i - x3i;                                     \
    float e1r = d1r * w0i + d1i * w0r, e1i = -d1r * w0r + d1i * w0i;            \
    sR[a0] = u0r + u1r; sI[a0] = u0i + u1i;                                     \
    float f0r = u0r - u1r, f0i = u0i - u1i;                                     \
    sR[a1] = f0r * w1r - f0i * w1i; sI[a1] = f0r * w1i + f0i * w1r;             \
    sR[a2] = e0r + e1r; sI[a2] = e0i + e1i;                                     \
    float f1r = e0r - e1r, f1i = e0i - e1i;                                     \
    sR[a3] = f1r * w1r - f1i * w1i; sI[a3] = f1r * w1i + f1i * w1r;             \
}

#define INV_DOUBLE(sR, sI, twR, twI, bi, t)                                     \
{                                                                               \
    const int h = 1 << (t);                                                     \
    int q = (bi) & (h - 1);                                                     \
    int B = (bi) >> (t);                                                        \
    int e0 = B * (h << 2) + q;                                                  \
    int a0 = PD(e0), a1 = PD(e0 + h), a2 = PD(e0 + 2 * h), a3 = PD(e0 + 3 * h); \
    float x0r = sR[a0], x0i = sI[a0], x1r = sR[a1], x1i = sI[a1];               \
    float x2r = sR[a2], x2i = sI[a2], x3r = sR[a3], x3i = sI[a3];               \
    int i0 = PD(q << (9 - (t))), i1 = PD(q << (8 - (t)));                       \
    float c0r = twR[i0], c0i = -twI[i0];                                        \
    float c1r = twR[i1], c1i = -twI[i1];                                        \
    float t1r = c0r * x1r - c0i * x1i, t1i = c0r * x1i + c0i * x1r;             \
    float b0r = x0r + t1r, b0i = x0i + t1i, b1r = x0r - t1r, b1i = x0i - t1i;   \
    float t3r = c0r * x3r - c0i * x3i, t3i = c0r * x3i + c0i * x3r;             \
    float b2r = x2r + t3r, b2i = x2i + t3i, b3r = x2r - t3r, b3i = x2i - t3i;   \
    float t2r = c1r * b2r - c1i * b2i, t2i = c1r * b2i + c1i * b2r;             \
    sR[a0] = b0r + t2r; sI[a0] = b0i + t2i;                                     \
    sR[a2] = b0r - t2r; sI[a2] = b0i - t2i;                                     \
    float gr = -c1i, gi = c1r;                                                  \
    float t4r = gr * b3r - gi * b3i, t4i = gr * b3i + gi * b3r;                 \
    sR[a1] = b1r + t4r; sI[a1] = b1i + t4i;                                     \
    sR[a3] = b1r - t4r; sI[a3] = b1i - t4i;                                     \
}

// ------------------------- block reduce -------------------------
__device__ __forceinline__ float block_reduce_256(float v, float* red) {
    #pragma unroll
    for (int o = 16; o > 0; o >>= 1) v += __shfl_down_sync(0xffffffffu, v, o);
    int lane = threadIdx.x & 31, wid = threadIdx.x >> 5;
    if (lane == 0) red[wid] = v;
    __syncthreads();
    float s = 0.0f;
    if (wid == 0) {
        s = (lane < 8) ? red[lane] : 0.0f;
        #pragma unroll
        for (int o = 4; o > 0; o >>= 1) s += __shfl_down_sync(0xffffffffu, s, o);
    }
    return s;
}

// ------------------------- fused 3x smoothing + norm partials -------------------------
__global__ void smooth3_kernel(const float* __restrict__ su_ext,
                               const float* __restrict__ sv_ext) {
    __shared__ float t0[38][40];
    __shared__ float t1[38][40];
    __shared__ float red[8];
    int slab = blockIdx.y;
    int fb = slab >> 3, b = slab & 7;
    const float* src = (fb ? sv_ext : su_ext) + (b << 20);
    int tile = blockIdx.x;
    int ty0 = (tile >> 5) << 5;
    int tx0 = (tile & 31) << 5;
    int tid = threadIdx.x;

    for (int i = tid; i < 38 * 38; i += 256) {
        int ly = i / 38, lx = i - ly * 38;
        int gy = (ty0 + ly - 3) & 1023;
        int gx = (tx0 + lx - 3) & 1023;
        t0[ly][lx] = src[(gy << 10) + gx];
    }
    __syncthreads();
    for (int i = tid; i < 36 * 36; i += 256) {
        int ly = i / 36, lx = i - ly * 36;
        ly += 1; lx += 1;
        float c = t0[ly][lx];
        t1[ly][lx] = c + 0.1f * (t0[ly][lx-1] + t0[ly][lx+1] + t0[ly-1][lx] + t0[ly+1][lx] - 4.0f * c);
    }
    __syncthreads();
    for (int i = tid; i < 34 * 34; i += 256) {
        int ly = i / 34, lx = i - ly * 34;
        ly += 2; lx += 2;
        float c = t1[ly][lx];
        t0[ly][lx] = c + 0.1f * (t1[ly][lx-1] + t1[ly][lx+1] + t1[ly-1][lx] + t1[ly+1][lx] - 4.0f * c);
    }
    __syncthreads();
    float ss = 0.0f;
    float* dst = g_fa + fb * BHW + (b << 20);
    for (int i = tid; i < 1024; i += 256) {
        int ly = (i >> 5) + 3, lx = (i & 31) + 3;
        float c = t0[ly][lx];
        float o = c + 0.1f * (t0[ly][lx-1] + t0[ly][lx+1] + t0[ly-1][lx] + t0[ly+1][lx] - 4.0f * c);
        dst[((ty0 + ly - 3) << 10) + (tx0 + lx - 3)] = o;
        ss += o * o;
    }
    float tot = block_reduce_256(ss, red);
    if (tid == 0) g_partials[slab * 1024 + tile] = tot;
}

__global__ void finalize_kernel() {
    int r = blockIdx.x;
    float s = 0.0f;
    for (int i = threadIdx.x; i < 1024; i += 256) s += g_partials[r * 1024 + i];
    __shared__ float red[8];
    float tot = block_reduce_256(s, red);
    if (threadIdx.x == 0) {
        float nrm = sqrtf(tot);
        g_invnorm[r] = 1.0f / fmaxf(nrm, 1e-12f);
    }
}

// ------------------------- main update (float4 vectorized) -------------------------
__global__ void update_kernel(const float* __restrict__ xin,
                              const float* __restrict__ beta) {
    int gid = blockIdx.x * 256 + threadIdx.x;          // over BHW/4
    int b  = gid >> 18;
    int t  = gid & 0x3FFFF;
    int y  = t >> 8;
    int x4 = (t & 255) << 2;
    int row = y << 10;
    int rp = ((y + 1) & 1023) << 10;
    int rm = ((y - 1) & 1023) << 10;
    int xm = (x4 - 1) & 1023, xp = (x4 + 4) & 1023;

    const float* u = xin + (size_t)(b * 3 + 0) * HW;
    const float* v = xin + (size_t)(b * 3 + 1) * HW;
    const float* p = xin + (size_t)(b * 3 + 2) * HW;

    float4 uc4  = *(const float4*)(u + row + x4);
    float4 uyp4 = *(const float4*)(u + rp + x4);
    float4 uym4 = *(const float4*)(u + rm + x4);
    float  uml  = u[row + xm], upr = u[row + xp];

    float4 vc4  = *(const float4*)(v + row + x4);
    float4 vyp4 = *(const float4*)(v + rp + x4);
    float4 vym4 = *(const float4*)(v + rm + x4);
    float  vml  = v[row + xm], vpr = v[row + xp];

    float4 pc4  = *(const float4*)(p + row + x4);
    float4 pyp4 = *(const float4*)(p + rp + x4);
    float4 pym4 = *(const float4*)(p + rm + x4);
    float  pml  = p[row + xm], ppr = p[row + xp];

    float4 fu4 = *(const float4*)(g_fa + (b << 20) + row + x4);
    float4 fv4 = *(const float4*)(g_fa + BHW + (b << 20) + row + x4);

    float sb = sqrtf(beta[b]);
    float inu = g_invnorm[b], inv_ = g_invnorm[8 + b];

    float uu[6] = {uml, uc4.x, uc4.y, uc4.z, uc4.w, upr};
    float vv[6] = {vml, vc4.x, vc4.y, vc4.z, vc4.w, vpr};
    float pp[6] = {pml, pc4.x, pc4.y, pc4.z, pc4.w, ppr};
    float uypA[4] = {uyp4.x, uyp4.y, uyp4.z, uyp4.w};
    float uymA[4] = {uym4.x, uym4.y, uym4.z, uym4.w};
    float vypA[4] = {vyp4.x, vyp4.y, vyp4.z, vyp4.w};
    float vymA[4] = {vym4.x, vym4.y, vym4.z, vym4.w};
    float pypA[4] = {pyp4.x, pyp4.y, pyp4.z, pyp4.w};
    float pymA[4] = {pym4.x, pym4.y, pym4.z, pym4.w};
    float fuA[4]  = {fu4.x, fu4.y, fu4.z, fu4.w};
    float fvA[4]  = {fv4.x, fv4.y, fv4.z, fv4.w};

    float uo[4], vo[4];
    #pragma unroll
    for (int i = 0; i < 4; i++) {
        float uc = uu[i + 1], vc = vv[i + 1];
        float adv_u = uc * 0.5f * (uu[i + 2] - uu[i]) + vc * 0.5f * (uypA[i] - uymA[i]);
        float adv_v = uc * 0.5f * (vv[i + 2] - vv[i]) + vc * 0.5f * (vypA[i] - vymA[i]);
        float lap_u = uu[i + 2] + uu[i] + uypA[i] + uymA[i] - 4.0f * uc;
        float lap_v = vv[i + 2] + vv[i] + vypA[i] + vymA[i] - 4.0f * vc;
        float dpdx = 0.5f * (pp[i + 2] - pp[i]);
        float dpdy = 0.5f * (pypA[i] - pymA[i]);
        uo[i] = uc + DT * (-adv_u + NU * lap_u - dpdx) + sb * (fuA[i] * inu);
        vo[i] = vc + DT * (-adv_v + NU * lap_v - dpdy) + sb * (fvA[i] * inv_);
    }
    *(float4*)(g_unew + (b << 20) + row + x4) = make_float4(uo[0], uo[1], uo[2], uo[3]);
    *(float4*)(g_vnew + (b << 20) + row + x4) = make_float4(vo[0], vo[1], vo[2], vo[3]);
}

// ------------------------- fwd FFT over x: one warp per packed row pair -------------------------
__global__ void __launch_bounds__(128) fft_fwd_div_kernel() {
    __shared__ float2 pool[4 * 1056];
    int tid = threadIdx.x, wid = tid >> 5, lane = tid & 31;
    int pairId = blockIdx.x * 4 + wid;       // b*512 + yp
    int b = pairId >> 9, yp = pairId & 511;
    int y0 = yp << 1, y1 = y0 + 1;
    int ub = b << 20;
    int r0 = y0 << 10, r1 = y1 << 10;
    int ym0 = ((y0 - 1) & 1023) << 10;
    int yp1 = ((y1 + 1) & 1023) << 10;

    float2 r[32];
    #pragma unroll
    for (int n1 = 0; n1 < 32; n1++) {
        int x = (n1 << 5) + lane;
        int xp = (x + 1) & 1023, xm = (x - 1) & 1023;
        float d0 = 0.5f * (g_unew[ub + r0 + xp] - g_unew[ub + r0 + xm])
                 + 0.5f * (g_vnew[ub + r1 + x]  - g_vnew[ub + ym0 + x]);
        float d1 = 0.5f * (g_unew[ub + r1 + xp] - g_unew[ub + r1 + xm])
                 + 0.5f * (g_vnew[ub + yp1 + x] - g_vnew[ub + r0 + x]);
        r[n1] = make_float2(d0, d1);
    }

    float2* zb = pool + wid * 1056;
    fft1024_warp(r, zb, lane);

    __syncwarp();
    #pragma unroll
    for (int k2 = 0; k2 < 32; k2++) zb[k2 * 33 + lane] = r[brev5(k2)];
    __syncwarp();

    float2* c0 = g_c1 + b * C1BATCH + y0 * C1ROW;
    float2* c1 = g_c1 + b * C1BATCH + y1 * C1ROW;
    #pragma unroll
    for (int m = 0; m < 17; m++) {
        int k = lane + (m << 5);
        if (k <= 512) {
            int km = (1024 - k) & 1023;
            float2 A = zb[(k >> 5) * 33 + (k & 31)];
            float2 B = zb[(km >> 5) * 33 + (km & 31)];
            c0[k] = make_float2(0.5f * (A.x + B.x), 0.5f * (A.y - B.y));
            c1[k] = make_float2(0.5f * (A.y + B.y), 0.5f * (B.x - A.x));
        }
    }
}

// ------------------------- fused column pipeline (block radix-4, natural kx) -------------------------
#define CS 1057
__global__ void fft_col_poisson_kernel() {
    __shared__ float sR[4 * CS], sI[4 * CS];
    __shared__ float twR[528], twI[528];

    int blk = blockIdx.x;                    // b*129 + g
    int b = blk / 129, g = blk - b * 129;
    int col0 = g << 2;
    int tid = threadIdx.x;                   // 256
    float2* base = g_c1 + b * C1BATCH;

    build_tw(twR, twI, tid);

    int c = tid & 3, yy = tid >> 2;
    int col = col0 + c;                      // natural spectral kx (valid cols <= 512; pad cols harmless)
    #pragma unroll
    for (int m = 0; m < 16; m++) {
        int y = yy + (m << 6);
        float2 v = base[y * C1ROW + col];
        sR[c * CS + PD(y)] = v.x; sI[c * CS + PD(y)] = v.y;
    }
    __syncthreads();

    int cc = tid >> 6, r = tid & 63;
    float* cR = sR + cc * CS;
    float* cI = sI + cc * CS;

    #pragma unroll
    for (int t = 0; t < 10; t += 2) {
        #pragma unroll
        for (int k = 0; k < 4; k++) {
            int bi = r + (k << 6);
            FWD_DOUBLE(cR, cI, twR, twI, bi, t);
        }
        __syncthreads();
    }

    // Poisson multiplier: y index bit-reversed (DIF output), kx natural
    float tkx = (float)min(col, 512);
    #pragma unroll
    for (int m = 0; m < 16; m++) {
        int ry = yy + (m << 6);
        int ky = brev10(ry);
        float tky = (float)min(ky, 1024 - ky);
        float k2 = tkx * tkx + tky * tky;
        float mm = (col == 0 && ky == 0) ? 0.0f
                 : (-1.0f / (39.47841760435743f * k2)) * (1.0f / 1024.0f);
        int a = c * CS + PD(ry);
        sR[a] *= mm; sI[a] *= mm;
    }
    __syncthreads();

    #pragma unroll
    for (int t = 0; t < 10; t += 2) {
        #pragma unroll
        for (int k = 0; k < 4; k++) {
            int bi = r + (k << 6);
            INV_DOUBLE(cR, cI, twR, twI, bi, t);
        }
        __syncthreads();
    }

    #pragma unroll
    for (int m = 0; m < 16; m++) {
        int y = yy + (m << 6);
        base[y * C1ROW + col] = make_float2(sR[c * CS + PD(y)], sI[c * CS + PD(y)]);
    }
}

// ------------------------- inverse FFT over x (block radix-4, PD-padded spectra stage) -------------------------
__global__ void fft_inv_real_kernel() {
    __shared__ float sR[1056], sI[1056];
    __shared__ float twR[528], twI[528];
    __shared__ float a1R[536], a1I[536], a2R[536], a2I[536];   // PD-padded (max PD(512)=528)

    int blk = blockIdx.x;                    // b*512 + yp
    int b = blk >> 9, yp = blk & 511;
    int y0 = yp << 1, y1 = y0 + 1;
    int tid = threadIdx.x;                   // 256

    build_tw(twR, twI, tid);
    const float2* c0 = g_c1 + b * C1BATCH + y0 * C1ROW;
    const float2* c1 = g_c1 + b * C1BATCH + y1 * C1ROW;
    #pragma unroll
    for (int k = 0; k < 2; k++) {
        int cc = tid + k * 256;
        float2 v1 = c0[cc], v2 = c1[cc];
        a1R[PD(cc)] = v1.x; a1I[PD(cc)] = v1.y;
        a2R[PD(cc)] = v2.x; a2I[PD(cc)] = v2.y;
    }
    if (tid == 0) {
        float2 v1 = c0[512], v2 = c1[512];
        a1R[PD(512)] = v1.x; a1I[PD(512)] = v1.y;
        a2R[PD(512)] = v2.x; a2I[PD(512)] = v2.y;
    }
    __syncthreads();

    // build packed spectrum B = S1 + i*S2 at DIF-bitrev storage position j (spectral k = brev(j))
    #pragma unroll
    for (int k = 0; k < 4; k++) {
        int j = tid + k * 256;
        int kk = brev10(j);
        float br, bi;
        if (kk <= 512) {
            int a = PD(kk);
            br = a1R[a] - a2I[a];
            bi = a1I[a] + a2R[a];
        } else {
            int a = PD(1024 - kk);
            br = a1R[a] + a2I[a];
            bi = -a1I[a] + a2R[a];
        }
        sR[PD(j)] = br; sI[PD(j)] = bi;
    }
    __syncthreads();

    #pragma unroll
    for (int t = 0; t < 10; t += 2) {
        INV_DOUBLE(sR, sI, twR, twI, tid, t);
        __syncthreads();
    }

    const float sc = 1.0f / 1024.0f;
    int bb = b << 20;
    #pragma unroll
    for (int k = 0; k < 4; k++) {
        int x = tid + k * 256;
        g_pcorr[bb + (y0 << 10) + x] = sR[PD(x)] * sc;
        g_pcorr[bb + (y1 << 10) + x] = sI[PD(x)] * sc;
    }
}

// ------------------------- final (float4 vectorized): subtract grad(p_corr), stack output -------------------------
__global__ void final_kernel(const float* __restrict__ xin, float* __restrict__ out) {
    int gid = blockIdx.x * 256 + threadIdx.x;          // over BHW/4
    int b  = gid >> 18;
    int t  = gid & 0x3FFFF;
    int y  = t >> 8;
    int x4 = (t & 255) << 2;
    int row = y << 10;
    int rp = ((y + 1) & 1023) << 10;
    int rm = ((y - 1) & 1023) << 10;
    int xm = (x4 - 1) & 1023, xp = (x4 + 4) & 1023;
    int bb = b << 20;

    const float* pc = g_pcorr + bb;
    float4 pcc4 = *(const float4*)(pc + row + x4);
    float4 pyp4 = *(const float4*)(pc + rp + x4);
    float4 pym4 = *(const float4*)(pc + rm + x4);
    float  pml  = pc[row + xm], ppr = pc[row + xp];

    float4 un4 = *(const float4*)(g_unew + bb + row + x4);
    float4 vn4 = *(const float4*)(g_vnew + bb + row + x4);
    float4 pin4 = *(const float4*)(xin + (size_t)(b * 3 + 2) * HW + row + x4);

    float ppx[6] = {pml, pcc4.x, pcc4.y, pcc4.z, pcc4.w, ppr};
    float pypA[4] = {pyp4.x, pyp4.y, pyp4.z, pyp4.w};
    float pymA[4] = {pym4.x, pym4.y, pym4.z, pym4.w};
    float unA[4] = {un4.x, un4.y, un4.z, un4.w};
    float vnA[4] = {vn4.x, vn4.y, vn4.z, vn4.w};
    float pinA[4] = {pin4.x, pin4.y, pin4.z, pin4.w};

    float uo[4], vo[4], po[4];
    #pragma unroll
    for (int i = 0; i < 4; i++) {
        uo[i] = unA[i] - 0.5f * (ppx[i + 2] - ppx[i]);
        vo[i] = vnA[i] - 0.5f * (pypA[i] - pymA[i]);
        po[i] = pinA[i] + ppx[i + 1];
    }
    *(float4*)(out + (size_t)(b * 3 + 0) * HW + row + x4) = make_float4(uo[0], uo[1], uo[2], uo[3]);
    *(float4*)(out + (size_t)(b * 3 + 1) * HW + row + x4) = make_float4(vo[0], vo[1], vo[2], vo[3]);
    *(float4*)(out + (size_t)(b * 3 + 2) * HW + row + x4) = make_float4(po[0], po[1], po[2], po[3]);
}

// ------------------------- launch -------------------------
extern "C" void kernel_launch(void* const* d_in, const int* in_sizes, int n_in,
                              void* d_out, int out_size) {
    (void)in_sizes; (void)n_in; (void)out_size;
    const float* x    = (const float*)d_in[0];
    const float* beta = (const float*)d_in[1];
    const float* fu   = (const float*)d_in[2];
    const float* fv   = (const float*)d_in[3];
    float* out = (float*)d_out;

    smooth3_kernel<<<dim3(1024, 16), 256>>>(fu, fv);
    finalize_kernel<<<16, 256>>>();
    update_kernel<<<BHW / 4 / 256, 256>>>(x, beta);
    fft_fwd_div_kernel<<<1024, 128>>>();
    fft_col_poisson_kernel<<<NB * 129, 256>>>();
    fft_inv_real_kernel<<<NB * 512, 256>>>();
    final_kernel<<<BHW / 4 / 256, 256>>>(x, out);
}

// round 15
// speedup vs baseline: 1.1157x; 1.0500x over previous
#include <cuda_runtime.h>
#include <math.h>

#define NB 8
#define NH 1024
#define NW 1024
#define HW (1 << 20)
#define BHW (NB * HW)

#define NU 0.01f
#define DT 0.01f

#define PD(i) ((i) + ((i) >> 5))

#define C1ROW 520                      // compact spectral row stride (slots 0..512 used, natural kx)
#define C1BATCH (1024 * C1ROW)

// ------------------------- device scratch -------------------------
__device__ float  g_fa[2 * BHW];
__device__ float  g_unew[BHW];
__device__ float  g_vnew[BHW];
__device__ float2 g_c1[NB * C1BATCH];
__device__ float  g_pcorr[BHW];
__device__ float  g_partials[16384];
__device__ float  g_invnorm[16];
__device__ float2 g_tw[512];           // tw[k] = exp(-2*pi*i*k/1024)

// ------------------------- complex helpers -------------------------
__device__ __forceinline__ float2 cmul(float2 a, float2 b) {
    return make_float2(a.x * b.x - a.y * b.y, a.x * b.y + a.y * b.x);
}
__device__ __forceinline__ float2 cadd(float2 a, float2 b) { return make_float2(a.x + b.x, a.y + b.y); }
__device__ __forceinline__ float2 csub(float2 a, float2 b) { return make_float2(a.x - b.x, a.y - b.y); }

__device__ __forceinline__ constexpr int brev5(int v) {
    return ((v & 1) << 4) | ((v & 2) << 2) | (v & 4) | ((v & 8) >> 2) | ((v & 16) >> 4);
}
__device__ __forceinline__ int brev10(int v) { return (int)(__brev((unsigned)v) >> 22); }

// W_32^q = exp(-2*pi*i*q/32), q=0..15
__constant__ float2 W32C[16] = {
    { 1.000000000f, -0.000000000f}, { 0.980785280f, -0.195090322f},
    { 0.923879533f, -0.382683432f}, { 0.831469612f, -0.555570233f},
    { 0.707106781f, -0.707106781f}, { 0.555570233f, -0.831469612f},
    { 0.382683432f, -0.923879533f}, { 0.195090322f, -0.980785280f},
    { 0.000000000f, -1.000000000f}, {-0.195090322f, -0.980785280f},
    {-0.382683432f, -0.923879533f}, {-0.555570233f, -0.831469612f},
    {-0.707106781f, -0.707106781f}, {-0.831469612f, -0.555570233f},
    {-0.923879533f, -0.382683432f}, {-0.980785280f, -0.195090322f},
};

// ------------------------- twiddle table init (1 tiny launch) -------------------------
__global__ void fill_tw_kernel() {
    int j = blockIdx.x * 256 + threadIdx.x;      // [0,512)
    float sn, cs;
    sincosf(-6.283185307179586f * (float)j * (1.0f / 1024.0f), &sn, &cs);
    g_tw[j] = make_float2(cs, sn);
}

// 32-pt in-place DIF (natural in, X[k] at r[brev5(k)])
__device__ __forceinline__ void dif32(float2* r) {
    #pragma unroll
    for (int t = 0; t < 5; t++) {
        const int h = 16 >> t;
        #pragma unroll
        for (int g = 0; g < (16 / h); g++) {
            #pragma unroll
            for (int q = 0; q < h; q++) {
                int i0 = ((g * h) << 1) + q, i1 = i0 + h;
                float2 A = r[i0], B = r[i1];
                r[i0] = cadd(A, B);
                r[i1] = cmul(csub(A, B), W32C[q << t]);
            }
        }
    }
}

// Warp 1024-pt forward FFT. In: r[n1] = z[32*n1 + lane]. Out: r[j] = Z[32*brev5(j) + lane].
__device__ __forceinline__ void fft1024_warp(float2* r, float2* zb, int lane) {
    dif32(r);
    float sn, cs;
    sincosf((float)lane * -6.135923151542565e-3f, &sn, &cs);   // -2*pi*lane/1024
    float2 w1 = make_float2(cs, sn), w = w1;
    #pragma unroll
    for (int k1 = 1; k1 < 32; k1++) {
        r[brev5(k1)] = cmul(r[brev5(k1)], w);
        w = cmul(w, w1);
    }
    __syncwarp();
    #pragma unroll
    for (int k1 = 0; k1 < 32; k1++) zb[lane * 33 + k1] = r[brev5(k1)];
    __syncwarp();
    #pragma unroll
    for (int n2 = 0; n2 < 32; n2++) r[n2] = zb[n2 * 33 + lane];
    dif32(r);
}

// ------------------------- block radix-4 machinery -------------------------
__device__ __forceinline__ void build_tw(float* twR, float* twI, int tid) {
    #pragma unroll
    for (int k = 0; k < 2; k++) {
        int j = tid + k * 256;
        float2 w = g_tw[j];
        twR[PD(j)] = w.x; twI[PD(j)] = w.y;
    }
}

#define FWD_DOUBLE(sR, sI, twR, twI, bi, t)                                     \
{                                                                               \
    const int h = 512 >> (t), h2 = h >> 1;                                      \
    int q = (bi) & (h2 - 1);                                                    \
    int B = (bi) >> (8 - (t));                                                  \
    int adr = B * (h << 1) + q;                                                 \
    int a0 = PD(adr), a1 = PD(adr + h2), a2 = PD(adr + h), a3 = PD(adr + h + h2); \
    float x0r = sR[a0], x0i = sI[a0], x1r = sR[a1], x1i = sI[a1];               \
    float x2r = sR[a2], x2i = sI[a2], x3r = sR[a3], x3i = sI[a3];               \
    int i0 = PD(q << (t)), i1 = PD(q << ((t) + 1));                             \
    float w0r = twR[i0], w0i = twI[i0];                                         \
    float w1r = twR[i1], w1i = twI[i1];                                         \
    float u0r = x0r + x2r, u0i = x0i + x2i;                                     \
    float d0r = x0r - x2r, d0i = x0i - x2i;                                     \
    float e0r = d0r * w0r - d0i * w0i, e0i = d0r * w0i + d0i * w0r;             \
    float u1r = x1r + x3r, u1i = x1i + x3i;                                     \
    float d1r = x1r - x3r, d1i = x1i - x3i;                                     \
    float e1r = d1r * w0i + d1i * w0r, e1i = -d1r * w0r + d1i * w0i;            \
    sR[a0] = u0r + u1r; sI[a0] = u0i + u1i;                                     \
    float f0r = u0r - u1r, f0i = u0i - u1i;                                     \
    sR[a1] = f0r * w1r - f0i * w1i; sI[a1] = f0r * w1i + f0i * w1r;             \
    sR[a2] = e0r + e1r; sI[a2] = e0i + e1i;                                     \
    float f1r = e0r - e1r, f1i = e0i - e1i;                                     \
    sR[a3] = f1r * w1r - f1i * w1i; sI[a3] = f1r * w1i + f1i * w1r;             \
}

#define INV_DOUBLE(sR, sI, twR, twI, bi, t)                                     \
{                                                                               \
    const int h = 1 << (t);                                                     \
    int q = (bi) & (h - 1);                                                     \
    int B = (bi) >> (t);                                                        \
    int e0 = B * (h << 2) + q;                                                  \
    int a0 = PD(e0), a1 = PD(e0 + h), a2 = PD(e0 + 2 * h), a3 = PD(e0 + 3 * h); \
    float x0r = sR[a0], x0i = sI[a0], x1r = sR[a1], x1i = sI[a1];               \
    float x2r = sR[a2], x2i = sI[a2], x3r = sR[a3], x3i = sI[a3];               \
    int i0 = PD(q << (9 - (t))), i1 = PD(q << (8 - (t)));                       \
    float c0r = twR[i0], c0i = -twI[i0];                                        \
    float c1r = twR[i1], c1i = -twI[i1];                                        \
    float t1r = c0r * x1r - c0i * x1i, t1i = c0r * x1i + c0i * x1r;             \
    float b0r = x0r + t1r, b0i = x0i + t1i, b1r = x0r - t1r, b1i = x0i - t1i;   \
    float t3r = c0r * x3r - c0i * x3i, t3i = c0r * x3i + c0i * x3r;             \
    float b2r = x2r + t3r, b2i = x2i + t3i, b3r = x2r - t3r, b3i = x2i - t3i;   \
    float t2r = c1r * b2r - c1i * b2i, t2i = c1r * b2i + c1i * b2r;             \
    sR[a0] = b0r + t2r; sI[a0] = b0i + t2i;                                     \
    sR[a2] = b0r - t2r; sI[a2] = b0i - t2i;                                     \
    float gr = -c1i, gi = c1r;                                                  \
    float t4r = gr * b3r - gi * b3i, t4i = gr * b3i + gi * b3r;                 \
    sR[a1] = b1r + t4r; sI[a1] = b1i + t4i;                                     \
    sR[a3] = b1r - t4r; sI[a3] = b1i - t4i;                                     \
}

// ------------------------- block reduce -------------------------
__device__ __forceinline__ float block_reduce_256(float v, float* red) {
    #pragma unroll
    for (int o = 16; o > 0; o >>= 1) v += __shfl_down_sync(0xffffffffu, v, o);
    int lane = threadIdx.x & 31, wid = threadIdx.x >> 5;
    if (lane == 0) red[wid] = v;
    __syncthreads();
    float s = 0.0f;
    if (wid == 0) {
        s = (lane < 8) ? red[lane] : 0.0f;
        #pragma unroll
        for (int o = 4; o > 0; o >>= 1) s += __shfl_down_sync(0xffffffffu, s, o);
    }
    return s;
}

// ------------------------- fused 3x smoothing + norm partials -------------------------
__global__ void smooth3_kernel(const float* __restrict__ su_ext,
                               const float* __restrict__ sv_ext) {
    __shared__ float t0[38][40];
    __shared__ float t1[38][40];
    __shared__ float red[8];
    int slab = blockIdx.y;
    int fb = slab >> 3, b = slab & 7;
    const float* src = (fb ? sv_ext : su_ext) + (b << 20);
    int tile = blockIdx.x;
    int ty0 = (tile >> 5) << 5;
    int tx0 = (tile & 31) << 5;
    int tid = threadIdx.x;

    for (int i = tid; i < 38 * 38; i += 256) {
        int ly = i / 38, lx = i - ly * 38;
        int gy = (ty0 + ly - 3) & 1023;
        int gx = (tx0 + lx - 3) & 1023;
        t0[ly][lx] = src[(gy << 10) + gx];
    }
    __syncthreads();
    for (int i = tid; i < 36 * 36; i += 256) {
        int ly = i / 36, lx = i - ly * 36;
        ly += 1; lx += 1;
        float c = t0[ly][lx];
        t1[ly][lx] = c + 0.1f * (t0[ly][lx-1] + t0[ly][lx+1] + t0[ly-1][lx] + t0[ly+1][lx] - 4.0f * c);
    }
    __syncthreads();
    for (int i = tid; i < 34 * 34; i += 256) {
        int ly = i / 34, lx = i - ly * 34;
        ly += 2; lx += 2;
        float c = t1[ly][lx];
        t0[ly][lx] = c + 0.1f * (t1[ly][lx-1] + t1[ly][lx+1] + t1[ly-1][lx] + t1[ly+1][lx] - 4.0f * c);
    }
    __syncthreads();
    float ss = 0.0f;
    float* dst = g_fa + fb * BHW + (b << 20);
    for (int i = tid; i < 1024; i += 256) {
        int ly = (i >> 5) + 3, lx = (i & 31) + 3;
        float c = t0[ly][lx];
        float o = c + 0.1f * (t0[ly][lx-1] + t0[ly][lx+1] + t0[ly-1][lx] + t0[ly+1][lx] - 4.0f * c);
        dst[((ty0 + ly - 3) << 10) + (tx0 + lx - 3)] = o;
        ss += o * o;
    }
    float tot = block_reduce_256(ss, red);
    if (tid == 0) g_partials[slab * 1024 + tile] = tot;
}

__global__ void finalize_kernel() {
    int r = blockIdx.x;
    float s = 0.0f;
    for (int i = threadIdx.x; i < 1024; i += 256) s += g_partials[r * 1024 + i];
    __shared__ float red[8];
    float tot = block_reduce_256(s, red);
    if (threadIdx.x == 0) {
        float nrm = sqrtf(tot);
        g_invnorm[r] = 1.0f / fmaxf(nrm, 1e-12f);
    }
}

// ------------------------- main update (float4 vectorized) -------------------------
__global__ void update_kernel(const float* __restrict__ xin,
                              const float* __restrict__ beta) {
    int gid = blockIdx.x * 256 + threadIdx.x;          // over BHW/4
    int b  = gid >> 18;
    int t  = gid & 0x3FFFF;
    int y  = t >> 8;
    int x4 = (t & 255) << 2;
    int row = y << 10;
    int rp = ((y + 1) & 1023) << 10;
    int rm = ((y - 1) & 1023) << 10;
    int xm = (x4 - 1) & 1023, xp = (x4 + 4) & 1023;

    const float* u = xin + (size_t)(b * 3 + 0) * HW;
    const float* v = xin + (size_t)(b * 3 + 1) * HW;
    const float* p = xin + (size_t)(b * 3 + 2) * HW;

    float4 uc4  = *(const float4*)(u + row + x4);
    float4 uyp4 = *(const float4*)(u + rp + x4);
    float4 uym4 = *(const float4*)(u + rm + x4);
    float  uml  = u[row + xm], upr = u[row + xp];

    float4 vc4  = *(const float4*)(v + row + x4);
    float4 vyp4 = *(const float4*)(v + rp + x4);
    float4 vym4 = *(const float4*)(v + rm + x4);
    float  vml  = v[row + xm], vpr = v[row + xp];

    float4 pc4  = *(const float4*)(p + row + x4);
    float4 pyp4 = *(const float4*)(p + rp + x4);
    float4 pym4 = *(const float4*)(p + rm + x4);
    float  pml  = p[row + xm], ppr = p[row + xp];

    float4 fu4 = *(const float4*)(g_fa + (b << 20) + row + x4);
    float4 fv4 = *(const float4*)(g_fa + BHW + (b << 20) + row + x4);

    float sb = sqrtf(beta[b]);
    float inu = g_invnorm[b], inv_ = g_invnorm[8 + b];

    float uu[6] = {uml, uc4.x, uc4.y, uc4.z, uc4.w, upr};
    float vv[6] = {vml, vc4.x, vc4.y, vc4.z, vc4.w, vpr};
    float pp[6] = {pml, pc4.x, pc4.y, pc4.z, pc4.w, ppr};
    float uypA[4] = {uyp4.x, uyp4.y, uyp4.z, uyp4.w};
    float uymA[4] = {uym4.x, uym4.y, uym4.z, uym4.w};
    float vypA[4] = {vyp4.x, vyp4.y, vyp4.z, vyp4.w};
    float vymA[4] = {vym4.x, vym4.y, vym4.z, vym4.w};
    float pypA[4] = {pyp4.x, pyp4.y, pyp4.z, pyp4.w};
    float pymA[4] = {pym4.x, pym4.y, pym4.z, pym4.w};
    float fuA[4]  = {fu4.x, fu4.y, fu4.z, fu4.w};
    float fvA[4]  = {fv4.x, fv4.y, fv4.z, fv4.w};

    float uo[4], vo[4];
    #pragma unroll
    for (int i = 0; i < 4; i++) {
        float uc = uu[i + 1], vc = vv[i + 1];
        float adv_u = uc * 0.5f * (uu[i + 2] - uu[i]) + vc * 0.5f * (uypA[i] - uymA[i]);
        float adv_v = uc * 0.5f * (vv[i + 2] - vv[i]) + vc * 0.5f * (vypA[i] - vymA[i]);
        float lap_u = uu[i + 2] + uu[i] + uypA[i] + uymA[i] - 4.0f * uc;
        float lap_v = vv[i + 2] + vv[i] + vypA[i] + vymA[i] - 4.0f * vc;
        float dpdx = 0.5f * (pp[i + 2] - pp[i]);
        float dpdy = 0.5f * (pypA[i] - pymA[i]);
        uo[i] = uc + DT * (-adv_u + NU * lap_u - dpdx) + sb * (fuA[i] * inu);
        vo[i] = vc + DT * (-adv_v + NU * lap_v - dpdy) + sb * (fvA[i] * inv_);
    }
    *(float4*)(g_unew + (b << 20) + row + x4) = make_float4(uo[0], uo[1], uo[2], uo[3]);
    *(float4*)(g_vnew + (b << 20) + row + x4) = make_float4(vo[0], vo[1], vo[2], vo[3]);
}

// ------------------------- fwd FFT over x: one warp per packed row pair -------------------------
__global__ void __launch_bounds__(128) fft_fwd_div_kernel() {
    __shared__ float2 pool[4 * 1056];
    int tid = threadIdx.x, wid = tid >> 5, lane = tid & 31;
    int pairId = blockIdx.x * 4 + wid;       // b*512 + yp
    int b = pairId >> 9, yp = pairId & 511;
    int y0 = yp << 1, y1 = y0 + 1;
    int ub = b << 20;
    int r0 = y0 << 10, r1 = y1 << 10;
    int ym0 = ((y0 - 1) & 1023) << 10;
    int yp1 = ((y1 + 1) & 1023) << 10;

    float2 r[32];
    #pragma unroll
    for (int n1 = 0; n1 < 32; n1++) {
        int x = (n1 << 5) + lane;
        int xp = (x + 1) & 1023, xm = (x - 1) & 1023;
        float d0 = 0.5f * (g_unew[ub + r0 + xp] - g_unew[ub + r0 + xm])
                 + 0.5f * (g_vnew[ub + r1 + x]  - g_vnew[ub + ym0 + x]);
        float d1 = 0.5f * (g_unew[ub + r1 + xp] - g_unew[ub + r1 + xm])
                 + 0.5f * (g_vnew[ub + yp1 + x] - g_vnew[ub + r0 + x]);
        r[n1] = make_float2(d0, d1);
    }

    float2* zb = pool + wid * 1056;
    fft1024_warp(r, zb, lane);

    __syncwarp();
    #pragma unroll
    for (int k2 = 0; k2 < 32; k2++) zb[k2 * 33 + lane] = r[brev5(k2)];
    __syncwarp();

    float2* c0 = g_c1 + b * C1BATCH + y0 * C1ROW;
    float2* c1 = g_c1 + b * C1BATCH + y1 * C1ROW;
    #pragma unroll
    for (int m = 0; m < 17; m++) {
        int k = lane + (m << 5);
        if (k <= 512) {
            int km = (1024 - k) & 1023;
            float2 A = zb[(k >> 5) * 33 + (k & 31)];
            float2 B = zb[(km >> 5) * 33 + (km & 31)];
            c0[k] = make_float2(0.5f * (A.x + B.x), 0.5f * (A.y - B.y));
            c1[k] = make_float2(0.5f * (A.y + B.y), 0.5f * (B.x - A.x));
        }
    }
}

// ------------------------- fused column pipeline (block radix-4, natural kx) -------------------------
#define CS 1057
__global__ void fft_col_poisson_kernel() {
    __shared__ float sR[4 * CS], sI[4 * CS];
    __shared__ float twR[528], twI[528];

    int blk = blockIdx.x;                    // b*129 + g
    int b = blk / 129, g = blk - b * 129;
    int col0 = g << 2;
    int tid = threadIdx.x;                   // 256
    float2* base = g_c1 + b * C1BATCH;

    build_tw(twR, twI, tid);

    int c = tid & 3, yy = tid >> 2;
    int col = col0 + c;                      // natural spectral kx (valid cols <= 512; pad cols harmless)
    #pragma unroll
    for (int m = 0; m < 16; m++) {
        int y = yy + (m << 6);
        float2 v = base[y * C1ROW + col];
        sR[c * CS + PD(y)] = v.x; sI[c * CS + PD(y)] = v.y;
    }
    __syncthreads();

    int cc = tid >> 6, r = tid & 63;
    float* cR = sR + cc * CS;
    float* cI = sI + cc * CS;

    #pragma unroll
    for (int t = 0; t < 10; t += 2) {
        #pragma unroll
        for (int k = 0; k < 4; k++) {
            int bi = r + (k << 6);
            FWD_DOUBLE(cR, cI, twR, twI, bi, t);
        }
        __syncthreads();
    }

    // Poisson multiplier: y index bit-reversed (DIF output), kx natural
    float tkx = (float)min(col, 512);
    #pragma unroll
    for (int m = 0; m < 16; m++) {
        int ry = yy + (m << 6);
        int ky = brev10(ry);
        float tky = (float)min(ky, 1024 - ky);
        float k2 = tkx * tkx + tky * tky;
        float mm = (col == 0 && ky == 0) ? 0.0f
                 : (-1.0f / (39.47841760435743f * k2)) * (1.0f / 1024.0f);
        int a = c * CS + PD(ry);
        sR[a] *= mm; sI[a] *= mm;
    }
    __syncthreads();

    #pragma unroll
    for (int t = 0; t < 10; t += 2) {
        #pragma unroll
        for (int k = 0; k < 4; k++) {
            int bi = r + (k << 6);
            INV_DOUBLE(cR, cI, twR, twI, bi, t);
        }
        __syncthreads();
    }

    #pragma unroll
    for (int m = 0; m < 16; m++) {
        int y = yy + (m << 6);
        base[y * C1ROW + col] = make_float2(sR[c * CS + PD(y)], sI[c * CS + PD(y)]);
    }
}

// ------------------------- inverse FFT over x (block radix-4, PD-padded spectra stage) -------------------------
__global__ void fft_inv_real_kernel() {
    __shared__ float sR[1056], sI[1056];
    __shared__ float twR[528], twI[528];
    __shared__ float a1R[536], a1I[536], a2R[536], a2I[536];   // PD-padded (max PD(512)=528)

    int blk = blockIdx.x;                    // b*512 + yp
    int b = blk >> 9, yp = blk & 511;
    int y0 = yp << 1, y1 = y0 + 1;
    int tid = threadIdx.x;                   // 256

    build_tw(twR, twI, tid);
    const float2* c0 = g_c1 + b * C1BATCH + y0 * C1ROW;
    const float2* c1 = g_c1 + b * C1BATCH + y1 * C1ROW;
    #pragma unroll
    for (int k = 0; k < 2; k++) {
        int cc = tid + k * 256;
        float2 v1 = c0[cc], v2 = c1[cc];
        a1R[PD(cc)] = v1.x; a1I[PD(cc)] = v1.y;
        a2R[PD(cc)] = v2.x; a2I[PD(cc)] = v2.y;
    }
    if (tid == 0) {
        float2 v1 = c0[512], v2 = c1[512];
        a1R[PD(512)] = v1.x; a1I[PD(512)] = v1.y;
        a2R[PD(512)] = v2.x; a2I[PD(512)] = v2.y;
    }
    __syncthreads();

    // build packed spectrum B = S1 + i*S2 at DIF-bitrev storage position j (spectral k = brev(j))
    #pragma unroll
    for (int k = 0; k < 4; k++) {
        int j = tid + k * 256;
        int kk = brev10(j);
        float br, bi;
        if (kk <= 512) {
            int a = PD(kk);
            br = a1R[a] - a2I[a];
            bi = a1I[a] + a2R[a];
        } else {
            int a = PD(1024 - kk);
            br = a1R[a] + a2I[a];
            bi = -a1I[a] + a2R[a];
        }
        sR[PD(j)] = br; sI[PD(j)] = bi;
    }
    __syncthreads();

    #pragma unroll
    for (int t = 0; t < 10; t += 2) {
        INV_DOUBLE(sR, sI, twR, twI, tid, t);
        __syncthreads();
    }

    const float sc = 1.0f / 1024.0f;
    int bb = b << 20;
    #pragma unroll
    for (int k = 0; k < 4; k++) {
        int x = tid + k * 256;
        g_pcorr[bb + (y0 << 10) + x] = sR[PD(x)] * sc;
        g_pcorr[bb + (y1 << 10) + x] = sI[PD(x)] * sc;
    }
}

// ------------------------- final (float4 vectorized): subtract grad(p_corr), stack output -------------------------
__global__ void final_kernel(const float* __restrict__ xin, float* __restrict__ out) {
    int gid = blockIdx.x * 256 + threadIdx.x;          // over BHW/4
    int b  = gid >> 18;
    int t  = gid & 0x3FFFF;
    int y  = t >> 8;
    int x4 = (t & 255) << 2;
    int row = y << 10;
    int rp = ((y + 1) & 1023) << 10;
    int rm = ((y - 1) & 1023) << 10;
    int xm = (x4 - 1) & 1023, xp = (x4 + 4) & 1023;
    int bb = b << 20;

    const float* pc = g_pcorr + bb;
    float4 pcc4 = *(const float4*)(pc + row + x4);
    float4 pyp4 = *(const float4*)(pc + rp + x4);
    float4 pym4 = *(const float4*)(pc + rm + x4);
    float  pml  = pc[row + xm], ppr = pc[row + xp];

    float4 un4 = *(const float4*)(g_unew + bb + row + x4);
    float4 vn4 = *(const float4*)(g_vnew + bb + row + x4);
    float4 pin4 = *(const float4*)(xin + (size_t)(b * 3 + 2) * HW + row + x4);

    float ppx[6] = {pml, pcc4.x, pcc4.y, pcc4.z, pcc4.w, ppr};
    float pypA[4] = {pyp4.x, pyp4.y, pyp4.z, pyp4.w};
    float pymA[4] = {pym4.x, pym4.y, pym4.z, pym4.w};
    float unA[4] = {un4.x, un4.y, un4.z, un4.w};
    float vnA[4] = {vn4.x, vn4.y, vn4.z, vn4.w};
    float pinA[4] = {pin4.x, pin4.y, pin4.z, pin4.w};

    float uo[4], vo[4], po[4];
    #pragma unroll
    for (int i = 0; i < 4; i++) {
        uo[i] = unA[i] - 0.5f * (ppx[i + 2] - ppx[i]);
        vo[i] = vnA[i] - 0.5f * (pypA[i] - pymA[i]);
        po[i] = pinA[i] + ppx[i + 1];
    }
    *(float4*)(out + (size_t)(b * 3 + 0) * HW + row + x4) = make_float4(uo[0], uo[1], uo[2], uo[3]);
    *(float4*)(out + (size_t)(b * 3 + 1) * HW + row + x4) = make_float4(vo[0], vo[1], vo[2], vo[3]);
    *(float4*)(out + (size_t)(b * 3 + 2) * HW + row + x4) = make_float4(po[0], po[1], po[2], po[3]);
}

// ------------------------- launch -------------------------
extern "C" void kernel_launch(void* const* d_in, const int* in_sizes, int n_in,
                              void* d_out, int out_size) {
    (void)in_sizes; (void)n_in; (void)out_size;
    const float* x    = (const float*)d_in[0];
    const float* beta = (const float*)d_in[1];
    const float* fu   = (const float*)d_in[2];
    const float* fv   = (const float*)d_in[3];
    float* out = (float*)d_out;

    fill_tw_kernel<<<2, 256>>>();
    smooth3_kernel<<<dim3(1024, 16), 256>>>(fu, fv);
    finalize_kernel<<<16, 256>>>();
    update_kernel<<<BHW / 4 / 256, 256>>>(x, beta);
    fft_fwd_div_kernel<<<1024, 128>>>();
    fft_col_poisson_kernel<<<NB * 129, 256>>>();
    fft_inv_real_kernel<<<NB * 512, 256>>>();
    final_kernel<<<BHW / 4 / 256, 256>>>(x, out);
}

// round 16
// speedup vs baseline: 1.1532x; 1.0336x over previous
#include <cuda_runtime.h>
#include <math.h>

#define NB 8
#define NH 1024
#define NW 1024
#define HW (1 << 20)
#define BHW (NB * HW)

#define NU 0.01f
#define DT 0.01f

#define PD(i) ((i) + ((i) >> 5))

#define C1ROW 520
#define C1BATCH (1024 * C1ROW)

// ------------------------- device scratch -------------------------
__device__ float  g_fa[2 * BHW];
__device__ float  g_unew[BHW];
__device__ float  g_vnew[BHW];
__device__ float2 g_c1[NB * C1BATCH];
__device__ float  g_pcorr[BHW];
__device__ float  g_partials[16384];
__device__ float  g_invnorm[16];
__device__ float2 g_tw[512];           // tw[k] = exp(-2*pi*i*k/1024)

// ------------------------- complex helpers -------------------------
__device__ __forceinline__ float2 cmul(float2 a, float2 b) {
    return make_float2(a.x * b.x - a.y * b.y, a.x * b.y + a.y * b.x);
}
__device__ __forceinline__ float2 cadd(float2 a, float2 b) { return make_float2(a.x + b.x, a.y + b.y); }
__device__ __forceinline__ float2 csub(float2 a, float2 b) { return make_float2(a.x - b.x, a.y - b.y); }

__device__ __forceinline__ constexpr int brev5(int v) {
    return ((v & 1) << 4) | ((v & 2) << 2) | (v & 4) | ((v & 8) >> 2) | ((v & 16) >> 4);
}
__device__ __forceinline__ int brev10(int v) { return (int)(__brev((unsigned)v) >> 22); }

__constant__ float2 W32C[16] = {
    { 1.000000000f, -0.000000000f}, { 0.980785280f, -0.195090322f},
    { 0.923879533f, -0.382683432f}, { 0.831469612f, -0.555570233f},
    { 0.707106781f, -0.707106781f}, { 0.555570233f, -0.831469612f},
    { 0.382683432f, -0.923879533f}, { 0.195090322f, -0.980785280f},
    { 0.000000000f, -1.000000000f}, {-0.195090322f, -0.980785280f},
    {-0.382683432f, -0.923879533f}, {-0.555570233f, -0.831469612f},
    {-0.707106781f, -0.707106781f}, {-0.831469612f, -0.555570233f},
    {-0.923879533f, -0.382683432f}, {-0.980785280f, -0.195090322f},
};

__global__ void fill_tw_kernel() {
    int j = blockIdx.x * 256 + threadIdx.x;      // [0,512)
    float sn, cs;
    sincosf(-6.283185307179586f * (float)j * (1.0f / 1024.0f), &sn, &cs);
    g_tw[j] = make_float2(cs, sn);
}

// 32-pt in-place DIF (natural in, X[k] at r[brev5(k)])
__device__ __forceinline__ void dif32(float2* r) {
    #pragma unroll
    for (int t = 0; t < 5; t++) {
        const int h = 16 >> t;
        #pragma unroll
        for (int g = 0; g < (16 / h); g++) {
            #pragma unroll
            for (int q = 0; q < h; q++) {
                int i0 = ((g * h) << 1) + q, i1 = i0 + h;
                float2 A = r[i0], B = r[i1];
                r[i0] = cadd(A, B);
                r[i1] = cmul(csub(A, B), W32C[q << t]);
            }
        }
    }
}

// Warp 1024-pt forward FFT. In: r[n1] = z[32*n1 + lane]. Out: r[j] = Z[32*brev5(j) + lane].
__device__ __forceinline__ void fft1024_warp(float2* r, float2* zb, int lane) {
    dif32(r);
    float sn, cs;
    sincosf((float)lane * -6.135923151542565e-3f, &sn, &cs);
    float2 w1 = make_float2(cs, sn), w = w1;
    #pragma unroll
    for (int k1 = 1; k1 < 32; k1++) {
        r[brev5(k1)] = cmul(r[brev5(k1)], w);
        w = cmul(w, w1);
    }
    __syncwarp();
    #pragma unroll
    for (int k1 = 0; k1 < 32; k1++) zb[lane * 33 + k1] = r[brev5(k1)];
    __syncwarp();
    #pragma unroll
    for (int n2 = 0; n2 < 32; n2++) r[n2] = zb[n2 * 33 + lane];
    dif32(r);
}

// ------------------------- block FFT machinery -------------------------
__device__ __forceinline__ void build_tw(float* twR, float* twI, int tid) {
    #pragma unroll
    for (int k = 0; k < 2; k++) {
        int j = tid + k * 256;
        float2 w = g_tw[j];
        twR[PD(j)] = w.x; twI[PD(j)] = w.y;
    }
}

#define FWD_DOUBLE(sR, sI, twR, twI, bi, t)                                     \
{                                                                               \
    const int h = 512 >> (t), h2 = h >> 1;                                      \
    int q = (bi) & (h2 - 1);                                                    \
    int B = (bi) >> (8 - (t));                                                  \
    int adr = B * (h << 1) + q;                                                 \
    int a0 = PD(adr), a1 = PD(adr + h2), a2 = PD(adr + h), a3 = PD(adr + h + h2); \
    float x0r = sR[a0], x0i = sI[a0], x1r = sR[a1], x1i = sI[a1];               \
    float x2r = sR[a2], x2i = sI[a2], x3r = sR[a3], x3i = sI[a3];               \
    int i0 = PD(q << (t)), i1 = PD(q << ((t) + 1));                             \
    float w0r = twR[i0], w0i = twI[i0];                                         \
    float w1r = twR[i1], w1i = twI[i1];                                         \
    float u0r = x0r + x2r, u0i = x0i + x2i;                                     \
    float d0r = x0r - x2r, d0i = x0i - x2i;                                     \
    float e0r = d0r * w0r - d0i * w0i, e0i = d0r * w0i + d0i * w0r;             \
    float u1r = x1r + x3r, u1i = x1i + x3i;                                     \
    float d1r = x1r - x3r, d1i = x1i - x3i;                                     \
    float e1r = d1r * w0i + d1i * w0r, e1i = -d1r * w0r + d1i * w0i;            \
    sR[a0] = u0r + u1r; sI[a0] = u0i + u1i;                                     \
    float f0r = u0r - u1r, f0i = u0i - u1i;                                     \
    sR[a1] = f0r * w1r - f0i * w1i; sI[a1] = f0r * w1i + f0i * w1r;             \
    sR[a2] = e0r + e1r; sI[a2] = e0i + e1i;                                     \
    float f1r = e0r - e1r, f1i = e0i - e1i;                                     \
    sR[a3] = f1r * w1r - f1i * w1i; sI[a3] = f1r * w1i + f1i * w1r;             \
}

#define INV_DOUBLE(sR, sI, twR, twI, bi, t)                                     \
{                                                                               \
    const int h = 1 << (t);                                                     \
    int q = (bi) & (h - 1);                                                     \
    int B = (bi) >> (t);                                                        \
    int e0 = B * (h << 2) + q;                                                  \
    int a0 = PD(e0), a1 = PD(e0 + h), a2 = PD(e0 + 2 * h), a3 = PD(e0 + 3 * h); \
    float x0r = sR[a0], x0i = sI[a0], x1r = sR[a1], x1i = sI[a1];               \
    float x2r = sR[a2], x2i = sI[a2], x3r = sR[a3], x3i = sI[a3];               \
    int i0 = PD(q << (9 - (t))), i1 = PD(q << (8 - (t)));                       \
    float c0r = twR[i0], c0i = -twI[i0];                                        \
    float c1r = twR[i1], c1i = -twI[i1];                                        \
    float t1r = c0r * x1r - c0i * x1i, t1i = c0r * x1i + c0i * x1r;             \
    float b0r = x0r + t1r, b0i = x0i + t1i, b1r = x0r - t1r, b1i = x0i - t1i;   \
    float t3r = c0r * x3r - c0i * x3i, t3i = c0r * x3i + c0i * x3r;             \
    float b2r = x2r + t3r, b2i = x2i + t3i, b3r = x2r - t3r, b3i = x2i - t3i;   \
    float t2r = c1r * b2r - c1i * b2i, t2i = c1r * b2i + c1i * b2r;             \
    sR[a0] = b0r + t2r; sI[a0] = b0i + t2i;                                     \
    sR[a2] = b0r - t2r; sI[a2] = b0i - t2i;                                     \
    float gr = -c1i, gi = c1r;                                                  \
    float t4r = gr * b3r - gi * b3i, t4i = gr * b3i + gi * b3r;                 \
    sR[a1] = b1r + t4r; sI[a1] = b1i + t4i;                                     \
    sR[a3] = b1r - t4r; sI[a3] = b1i - t4i;                                     \
}

// ---- radix-16 fused pass: forward DIF stages t..t+3 (t compile-time 0 or 4) ----
// group gi in [0,64): h=512>>t, u=h/8, q=gi mod u, B=gi div u, base=B*2h+q.
__device__ __forceinline__ void fwd_quad(float* cR, float* cI,
                                         const float* twR, const float* twI,
                                         int gi, const int t) {
    const int h = 512 >> t, u = h >> 3;
    int q = gi & (u - 1);
    int B = gi >> (6 - t);                 // log2(u) = 6-t for t in {0,4}
    int base = B * (h << 1) + q;
    float xr[16], xi[16];
    #pragma unroll
    for (int m = 0; m < 16; m++) {
        int a = PD(base + m * u);
        xr[m] = cR[a]; xi[m] = cI[a];
    }
    // stage t: pairs (m, m+8), w = tw[(q + m*u) << t]
    #pragma unroll
    for (int m = 0; m < 8; m++) {
        int iw = PD((q + m * u) << t);
        float wr = twR[iw], wi = twI[iw];
        float ar = xr[m], ai = xi[m], br = xr[m + 8], bi = xi[m + 8];
        xr[m] = ar + br; xi[m] = ai + bi;
        float dr = ar - br, di = ai - bi;
        xr[m + 8] = dr * wr - di * wi; xi[m + 8] = dr * wi + di * wr;
    }
    // stage t+1: pairs (g+m2, g+m2+4), g in {0,8}, w = tw[(q + m2*u) << (t+1)]
    #pragma unroll
    for (int g = 0; g < 16; g += 8) {
        #pragma unroll
        for (int m2 = 0; m2 < 4; m2++) {
            int i0 = g + m2, i1 = i0 + 4;
            int iw = PD((q + m2 * u) << (t + 1));
            float wr = twR[iw], wi = twI[iw];
            float ar = xr[i0], ai = xi[i0], br = xr[i1], bi = xi[i1];
            xr[i0] = ar + br; xi[i0] = ai + bi;
            float dr = ar - br, di = ai - bi;
            xr[i1] = dr * wr - di * wi; xi[i1] = dr * wi + di * wr;
        }
    }
    // stage t+2: pairs (g+m2, g+m2+2), g in {0,4,8,12}, w = tw[(q + m2*u) << (t+2)]
    #pragma unroll
    for (int g = 0; g < 16; g += 4) {
        #pragma unroll
        for (int m2 = 0; m2 < 2; m2++) {
            int i0 = g + m2, i1 = i0 + 2;
            int iw = PD((q + m2 * u) << (t + 2));
            float wr = twR[iw], wi = twI[iw];
            float ar = xr[i0], ai = xi[i0], br = xr[i1], bi = xi[i1];
            xr[i0] = ar + br; xi[i0] = ai + bi;
            float dr = ar - br, di = ai - bi;
            xr[i1] = dr * wr - di * wi; xi[i1] = dr * wi + di * wr;
        }
    }
    // stage t+3: pairs (g, g+1), w = tw[q << (t+3)]
    {
        int iw = PD(q << (t + 3));
        float wr = twR[iw], wi = twI[iw];
        #pragma unroll
        for (int g = 0; g < 16; g += 2) {
            float ar = xr[g], ai = xi[g], br = xr[g + 1], bi = xi[g + 1];
            xr[g] = ar + br; xi[g] = ai + bi;
            float dr = ar - br, di = ai - bi;
            xr[g + 1] = dr * wr - di * wi; xi[g + 1] = dr * wi + di * wr;
        }
    }
    #pragma unroll
    for (int m = 0; m < 16; m++) {
        int a = PD(base + m * u);
        cR[a] = xr[m]; cI[a] = xi[m];
    }
}

// ---- radix-16 fused pass: inverse DIT stages t..t+3 (conj twiddles), t in {0,4} ----
// h=1<<t, q=gi mod h, B=gi div h, base=B*16h+q; points base+m*h.
__device__ __forceinline__ void inv_quad(float* cR, float* cI,
                                         const float* twR, const float* twI,
                                         int gi, const int t) {
    const int h = 1 << t;
    int q = gi & (h - 1);
    int B = gi >> t;
    int base = B * (h << 4) + q;
    float xr[16], xi[16];
    #pragma unroll
    for (int m = 0; m < 16; m++) {
        int a = PD(base + m * h);
        xr[m] = cR[a]; xi[m] = cI[a];
    }
    // stage t: pairs (g, g+1), w = conj(tw[q << (9-t)])
    {
        int iw = PD(q << (9 - t));
        float wr = twR[iw], wi = -twI[iw];
        #pragma unroll
        for (int g = 0; g < 16; g += 2) {
            float br = xr[g + 1], bi = xi[g + 1];
            float tr = wr * br - wi * bi, ti = wr * bi + wi * br;
            float ar = xr[g], ai = xi[g];
            xr[g] = ar + tr; xi[g] = ai + ti;
            xr[g + 1] = ar - tr; xi[g + 1] = ai - ti;
        }
    }
    // stage t+1: pairs (g+m2, g+m2+2), g in {0,4,8,12}, w = conj(tw[(q + m2*h) << (8-t)])
    #pragma unroll
    for (int g = 0; g < 16; g += 4) {
        #pragma unroll
        for (int m2 = 0; m2 < 2; m2++) {
            int i0 = g + m2, i1 = i0 + 2;
            int iw = PD((q + m2 * h) << (8 - t));
            float wr = twR[iw], wi = -twI[iw];
            float br = xr[i1], bi = xi[i1];
            float tr = wr * br - wi * bi, ti = wr * bi + wi * br;
            float ar = xr[i0], ai = xi[i0];
            xr[i0] = ar + tr; xi[i0] = ai + ti;
            xr[i1] = ar - tr; xi[i1] = ai - ti;
        }
    }
    // stage t+2: pairs (g+m2, g+m2+4), g in {0,8}, w = conj(tw[(q + m2*h) << (7-t)])
    #pragma unroll
    for (int g = 0; g < 16; g += 8) {
        #pragma unroll
        for (int m2 = 0; m2 < 4; m2++) {
            int i0 = g + m2, i1 = i0 + 4;
            int iw = PD((q + m2 * h) << (7 - t));
            float wr = twR[iw], wi = -twI[iw];
            float br = xr[i1], bi = xi[i1];
            float tr = wr * br - wi * bi, ti = wr * bi + wi * br;
            float ar = xr[i0], ai = xi[i0];
            xr[i0] = ar + tr; xi[i0] = ai + ti;
            xr[i1] = ar - tr; xi[i1] = ai - ti;
        }
    }
    // stage t+3: pairs (m2, m2+8), w = conj(tw[(q + m2*h) << (6-t)])
    #pragma unroll
    for (int m2 = 0; m2 < 8; m2++) {
        int iw = PD((q + m2 * h) << (6 - t));
        float wr = twR[iw], wi = -twI[iw];
        float br = xr[m2 + 8], bi = xi[m2 + 8];
        float tr = wr * br - wi * bi, ti = wr * bi + wi * br;
        float ar = xr[m2], ai = xi[m2];
        xr[m2] = ar + tr; xi[m2] = ai + ti;
        xr[m2 + 8] = ar - tr; xi[m2 + 8] = ai - ti;
    }
    #pragma unroll
    for (int m = 0; m < 16; m++) {
        int a = PD(base + m * h);
        cR[a] = xr[m]; cI[a] = xi[m];
    }
}

// ------------------------- block reduce -------------------------
__device__ __forceinline__ float block_reduce_256(float v, float* red) {
    #pragma unroll
    for (int o = 16; o > 0; o >>= 1) v += __shfl_down_sync(0xffffffffu, v, o);
    int lane = threadIdx.x & 31, wid = threadIdx.x >> 5;
    if (lane == 0) red[wid] = v;
    __syncthreads();
    float s = 0.0f;
    if (wid == 0) {
        s = (lane < 8) ? red[lane] : 0.0f;
        #pragma unroll
        for (int o = 4; o > 0; o >>= 1) s += __shfl_down_sync(0xffffffffu, s, o);
    }
    return s;
}

// ------------------------- fused 3x smoothing + norm partials -------------------------
__global__ void smooth3_kernel(const float* __restrict__ su_ext,
                               const float* __restrict__ sv_ext) {
    __shared__ float t0[38][40];
    __shared__ float t1[38][40];
    __shared__ float red[8];
    int slab = blockIdx.y;
    int fb = slab >> 3, b = slab & 7;
    const float* src = (fb ? sv_ext : su_ext) + (b << 20);
    int tile = blockIdx.x;
    int ty0 = (tile >> 5) << 5;
    int tx0 = (tile & 31) << 5;
    int tid = threadIdx.x;

    for (int i = tid; i < 38 * 38; i += 256) {
        int ly = i / 38, lx = i - ly * 38;
        int gy = (ty0 + ly - 3) & 1023;
        int gx = (tx0 + lx - 3) & 1023;
        t0[ly][lx] = src[(gy << 10) + gx];
    }
    __syncthreads();
    for (int i = tid; i < 36 * 36; i += 256) {
        int ly = i / 36, lx = i - ly * 36;
        ly += 1; lx += 1;
        float c = t0[ly][lx];
        t1[ly][lx] = c + 0.1f * (t0[ly][lx-1] + t0[ly][lx+1] + t0[ly-1][lx] + t0[ly+1][lx] - 4.0f * c);
    }
    __syncthreads();
    for (int i = tid; i < 34 * 34; i += 256) {
        int ly = i / 34, lx = i - ly * 34;
        ly += 2; lx += 2;
        float c = t1[ly][lx];
        t0[ly][lx] = c + 0.1f * (t1[ly][lx-1] + t1[ly][lx+1] + t1[ly-1][lx] + t1[ly+1][lx] - 4.0f * c);
    }
    __syncthreads();
    float ss = 0.0f;
    float* dst = g_fa + fb * BHW + (b << 20);
    for (int i = tid; i < 1024; i += 256) {
        int ly = (i >> 5) + 3, lx = (i & 31) + 3;
        float c = t0[ly][lx];
        float o = c + 0.1f * (t0[ly][lx-1] + t0[ly][lx+1] + t0[ly-1][lx] + t0[ly+1][lx] - 4.0f * c);
        dst[((ty0 + ly - 3) << 10) + (tx0 + lx - 3)] = o;
        ss += o * o;
    }
    float tot = block_reduce_256(ss, red);
    if (tid == 0) g_partials[slab * 1024 + tile] = tot;
}

__global__ void finalize_kernel() {
    int r = blockIdx.x;
    float s = 0.0f;
    for (int i = threadIdx.x; i < 1024; i += 256) s += g_partials[r * 1024 + i];
    __shared__ float red[8];
    float tot = block_reduce_256(s, red);
    if (threadIdx.x == 0) {
        float nrm = sqrtf(tot);
        g_invnorm[r] = 1.0f / fmaxf(nrm, 1e-12f);
    }
}

// ------------------------- main update (float4 vectorized) -------------------------
__global__ void update_kernel(const float* __restrict__ xin,
                              const float* __restrict__ beta) {
    int gid = blockIdx.x * 256 + threadIdx.x;          // over BHW/4
    int b  = gid >> 18;
    int t  = gid & 0x3FFFF;
    int y  = t >> 8;
    int x4 = (t & 255) << 2;
    int row = y << 10;
    int rp = ((y + 1) & 1023) << 10;
    int rm = ((y - 1) & 1023) << 10;
    int xm = (x4 - 1) & 1023, xp = (x4 + 4) & 1023;

    const float* u = xin + (size_t)(b * 3 + 0) * HW;
    const float* v = xin + (size_t)(b * 3 + 1) * HW;
    const float* p = xin + (size_t)(b * 3 + 2) * HW;

    float4 uc4  = *(const float4*)(u + row + x4);
    float4 uyp4 = *(const float4*)(u + rp + x4);
    float4 uym4 = *(const float4*)(u + rm + x4);
    float  uml  = u[row + xm], upr = u[row + xp];

    float4 vc4  = *(const float4*)(v + row + x4);
    float4 vyp4 = *(const float4*)(v + rp + x4);
    float4 vym4 = *(const float4*)(v + rm + x4);
    float  vml  = v[row + xm], vpr = v[row + xp];

    float4 pc4  = *(const float4*)(p + row + x4);
    float4 pyp4 = *(const float4*)(p + rp + x4);
    float4 pym4 = *(const float4*)(p + rm + x4);
    float  pml  = p[row + xm], ppr = p[row + xp];

    float4 fu4 = *(const float4*)(g_fa + (b << 20) + row + x4);
    float4 fv4 = *(const float4*)(g_fa + BHW + (b << 20) + row + x4);

    float sb = sqrtf(beta[b]);
    float inu = g_invnorm[b], inv_ = g_invnorm[8 + b];

    float uu[6] = {uml, uc4.x, uc4.y, uc4.z, uc4.w, upr};
    float vv[6] = {vml, vc4.x, vc4.y, vc4.z, vc4.w, vpr};
    float pp[6] = {pml, pc4.x, pc4.y, pc4.z, pc4.w, ppr};
    float uypA[4] = {uyp4.x, uyp4.y, uyp4.z, uyp4.w};
    float uymA[4] = {uym4.x, uym4.y, uym4.z, uym4.w};
    float vypA[4] = {vyp4.x, vyp4.y, vyp4.z, vyp4.w};
    float vymA[4] = {vym4.x, vym4.y, vym4.z, vym4.w};
    float pypA[4] = {pyp4.x, pyp4.y, pyp4.z, pyp4.w};
    float pymA[4] = {pym4.x, pym4.y, pym4.z, pym4.w};
    float fuA[4]  = {fu4.x, fu4.y, fu4.z, fu4.w};
    float fvA[4]  = {fv4.x, fv4.y, fv4.z, fv4.w};

    float uo[4], vo[4];
    #pragma unroll
    for (int i = 0; i < 4; i++) {
        float uc = uu[i + 1], vc = vv[i + 1];
        float adv_u = uc * 0.5f * (uu[i + 2] - uu[i]) + vc * 0.5f * (uypA[i] - uymA[i]);
        float adv_v = uc * 0.5f * (vv[i + 2] - vv[i]) + vc * 0.5f * (vypA[i] - vymA[i]);
        float lap_u = uu[i + 2] + uu[i] + uypA[i] + uymA[i] - 4.0f * uc;
        float lap_v = vv[i + 2] + vv[i] + vypA[i] + vymA[i] - 4.0f * vc;
        float dpdx = 0.5f * (pp[i + 2] - pp[i]);
        float dpdy = 0.5f * (pypA[i] - pymA[i]);
        uo[i] = uc + DT * (-adv_u + NU * lap_u - dpdx) + sb * (fuA[i] * inu);
        vo[i] = vc + DT * (-adv_v + NU * lap_v - dpdy) + sb * (fvA[i] * inv_);
    }
    *(float4*)(g_unew + (b << 20) + row + x4) = make_float4(uo[0], uo[1], uo[2], uo[3]);
    *(float4*)(g_vnew + (b << 20) + row + x4) = make_float4(vo[0], vo[1], vo[2], vo[3]);
}

// ------------------------- fwd FFT over x: one warp per packed row pair -------------------------
__global__ void __launch_bounds__(128) fft_fwd_div_kernel() {
    __shared__ float2 pool[4 * 1056];
    int tid = threadIdx.x, wid = tid >> 5, lane = tid & 31;
    int pairId = blockIdx.x * 4 + wid;       // b*512 + yp
    int b = pairId >> 9, yp = pairId & 511;
    int y0 = yp << 1, y1 = y0 + 1;
    int ub = b << 20;
    int r0 = y0 << 10, r1 = y1 << 10;
    int ym0 = ((y0 - 1) & 1023) << 10;
    int yp1 = ((y1 + 1) & 1023) << 10;

    float2 r[32];
    #pragma unroll
    for (int n1 = 0; n1 < 32; n1++) {
        int x = (n1 << 5) + lane;
        int xp = (x + 1) & 1023, xm = (x - 1) & 1023;
        float d0 = 0.5f * (g_unew[ub + r0 + xp] - g_unew[ub + r0 + xm])
                 + 0.5f * (g_vnew[ub + r1 + x]  - g_vnew[ub + ym0 + x]);
        float d1 = 0.5f * (g_unew[ub + r1 + xp] - g_unew[ub + r1 + xm])
                 + 0.5f * (g_vnew[ub + yp1 + x] - g_vnew[ub + r0 + x]);
        r[n1] = make_float2(d0, d1);
    }

    float2* zb = pool + wid * 1056;
    fft1024_warp(r, zb, lane);

    __syncwarp();
    #pragma unroll
    for (int k2 = 0; k2 < 32; k2++) zb[k2 * 33 + lane] = r[brev5(k2)];
    __syncwarp();

    float2* c0 = g_c1 + b * C1BATCH + y0 * C1ROW;
    float2* c1 = g_c1 + b * C1BATCH + y1 * C1ROW;
    #pragma unroll
    for (int m = 0; m < 17; m++) {
        int k = lane + (m << 5);
        if (k <= 512) {
            int km = (1024 - k) & 1023;
            float2 A = zb[(k >> 5) * 33 + (k & 31)];
            float2 B = zb[(km >> 5) * 33 + (km & 31)];
            c0[k] = make_float2(0.5f * (A.x + B.x), 0.5f * (A.y - B.y));
            c1[k] = make_float2(0.5f * (A.y + B.y), 0.5f * (B.x - A.x));
        }
    }
}

// ------------------------- fused column pipeline (radix-16 passes) -------------------------
#define CS 1057
__global__ void __launch_bounds__(256, 2) fft_col_poisson_kernel() {
    __shared__ float sR[4 * CS], sI[4 * CS];
    __shared__ float twR[528], twI[528];

    int blk = blockIdx.x;                    // b*129 + g
    int b = blk / 129, g = blk - b * 129;
    int col0 = g << 2;
    int tid = threadIdx.x;                   // 256
    float2* base = g_c1 + b * C1BATCH;

    build_tw(twR, twI, tid);

    int c = tid & 3, yy = tid >> 2;
    int col = col0 + c;
    #pragma unroll
    for (int m = 0; m < 16; m++) {
        int y = yy + (m << 6);
        float2 v = base[y * C1ROW + col];
        sR[c * CS + PD(y)] = v.x; sI[c * CS + PD(y)] = v.y;
    }
    __syncthreads();

    int cc = tid >> 6, r = tid & 63;
    float* cR = sR + cc * CS;
    float* cI = sI + cc * CS;

    // forward DIF: stages 0-3, 4-7 as radix-16 passes, then 8-9 as double
    fwd_quad(cR, cI, twR, twI, r, 0);
    __syncthreads();
    fwd_quad(cR, cI, twR, twI, r, 4);
    __syncthreads();
    #pragma unroll
    for (int k = 0; k < 4; k++) {
        int bi = r + (k << 6);
        FWD_DOUBLE(cR, cI, twR, twI, bi, 8);
    }
    __syncthreads();

    // Poisson multiplier: y index bit-reversed (DIF output), kx natural
    float tkx = (float)min(col, 512);
    #pragma unroll
    for (int m = 0; m < 16; m++) {
        int ry = yy + (m << 6);
        int ky = brev10(ry);
        float tky = (float)min(ky, 1024 - ky);
        float k2 = tkx * tkx + tky * tky;
        float mm = (col == 0 && ky == 0) ? 0.0f
                 : (-1.0f / (39.47841760435743f * k2)) * (1.0f / 1024.0f);
        int a = c * CS + PD(ry);
        sR[a] *= mm; sI[a] *= mm;
    }
    __syncthreads();

    // inverse DIT: stages 0-3, 4-7 as radix-16 passes, then 8-9 as double
    inv_quad(cR, cI, twR, twI, r, 0);
    __syncthreads();
    inv_quad(cR, cI, twR, twI, r, 4);
    __syncthreads();
    #pragma unroll
    for (int k = 0; k < 4; k++) {
        int bi = r + (k << 6);
        INV_DOUBLE(cR, cI, twR, twI, bi, 8);
    }
    __syncthreads();

    #pragma unroll
    for (int m = 0; m < 16; m++) {
        int y = yy + (m << 6);
        base[y * C1ROW + col] = make_float2(sR[c * CS + PD(y)], sI[c * CS + PD(y)]);
    }
}

// ------------------------- inverse FFT over x (block radix-4, PD-padded spectra stage) -------------------------
__global__ void fft_inv_real_kernel() {
    __shared__ float sR[1056], sI[1056];
    __shared__ float twR[528], twI[528];
    __shared__ float a1R[536], a1I[536], a2R[536], a2I[536];

    int blk = blockIdx.x;                    // b*512 + yp
    int b = blk >> 9, yp = blk & 511;
    int y0 = yp << 1, y1 = y0 + 1;
    int tid = threadIdx.x;                   // 256

    build_tw(twR, twI, tid);
    const float2* c0 = g_c1 + b * C1BATCH + y0 * C1ROW;
    const float2* c1 = g_c1 + b * C1BATCH + y1 * C1ROW;
    #pragma unroll
    for (int k = 0; k < 2; k++) {
        int cc = tid + k * 256;
        float2 v1 = c0[cc], v2 = c1[cc];
        a1R[PD(cc)] = v1.x; a1I[PD(cc)] = v1.y;
        a2R[PD(cc)] = v2.x; a2I[PD(cc)] = v2.y;
    }
    if (tid == 0) {
        float2 v1 = c0[512], v2 = c1[512];
        a1R[PD(512)] = v1.x; a1I[PD(512)] = v1.y;
        a2R[PD(512)] = v2.x; a2I[PD(512)] = v2.y;
    }
    __syncthreads();

    #pragma unroll
    for (int k = 0; k < 4; k++) {
        int j = tid + k * 256;
        int kk = brev10(j);
        float br, bi;
        if (kk <= 512) {
            int a = PD(kk);
            br = a1R[a] - a2I[a];
            bi = a1I[a] + a2R[a];
        } else {
            int a = PD(1024 - kk);
            br = a1R[a] + a2I[a];
            bi = -a1I[a] + a2R[a];
        }
        sR[PD(j)] = br; sI[PD(j)] = bi;
    }
    __syncthreads();

    #pragma unroll
    for (int t = 0; t < 10; t += 2) {
        INV_DOUBLE(sR, sI, twR, twI, tid, t);
        __syncthreads();
    }

    const float sc = 1.0f / 1024.0f;
    int bb = b << 20;
    #pragma unroll
    for (int k = 0; k < 4; k++) {
        int x = tid + k * 256;
        g_pcorr[bb + (y0 << 10) + x] = sR[PD(x)] * sc;
        g_pcorr[bb + (y1 << 10) + x] = sI[PD(x)] * sc;
    }
}

// ------------------------- final (float4 vectorized): subtract grad(p_corr), stack output -------------------------
__global__ void final_kernel(const float* __restrict__ xin, float* __restrict__ out) {
    int gid = blockIdx.x * 256 + threadIdx.x;          // over BHW/4
    int b  = gid >> 18;
    int t  = gid & 0x3FFFF;
    int y  = t >> 8;
    int x4 = (t & 255) << 2;
    int row = y << 10;
    int rp = ((y + 1) & 1023) << 10;
    int rm = ((y - 1) & 1023) << 10;
    int xm = (x4 - 1) & 1023, xp = (x4 + 4) & 1023;
    int bb = b << 20;

    const float* pc = g_pcorr + bb;
    float4 pcc4 = *(const float4*)(pc + row + x4);
    float4 pyp4 = *(const float4*)(pc + rp + x4);
    float4 pym4 = *(const float4*)(pc + rm + x4);
    float  pml  = pc[row + xm], ppr = pc[row + xp];

    float4 un4 = *(const float4*)(g_unew + bb + row + x4);
    float4 vn4 = *(const float4*)(g_vnew + bb + row + x4);
    float4 pin4 = *(const float4*)(xin + (size_t)(b * 3 + 2) * HW + row + x4);

    float ppx[6] = {pml, pcc4.x, pcc4.y, pcc4.z, pcc4.w, ppr};
    float pypA[4] = {pyp4.x, pyp4.y, pyp4.z, pyp4.w};
    float pymA[4] = {pym4.x, pym4.y, pym4.z, pym4.w};
    float unA[4] = {un4.x, un4.y, un4.z, un4.w};
    float vnA[4] = {vn4.x, vn4.y, vn4.z, vn4.w};
    float pinA[4] = {pin4.x, pin4.y, pin4.z, pin4.w};

    float uo[4], vo[4], po[4];
    #pragma unroll
    for (int i = 0; i < 4; i++) {
        uo[i] = unA[i] - 0.5f * (ppx[i + 2] - ppx[i]);
        vo[i] = vnA[i] - 0.5f * (pypA[i] - pymA[i]);
        po[i] = pinA[i] + ppx[i + 1];
    }
    *(float4*)(out + (size_t)(b * 3 + 0) * HW + row + x4) = make_float4(uo[0], uo[1], uo[2], uo[3]);
    *(float4*)(out + (size_t)(b * 3 + 1) * HW + row + x4) = make_float4(vo[0], vo[1], vo[2], vo[3]);
    *(float4*)(out + (size_t)(b * 3 + 2) * HW + row + x4) = make_float4(po[0], po[1], po[2], po[3]);
}

// ------------------------- launch -------------------------
extern "C" void kernel_launch(void* const* d_in, const int* in_sizes, int n_in,
                              void* d_out, int out_size) {
    (void)in_sizes; (void)n_in; (void)out_size;
    const float* x    = (const float*)d_in[0];
    const float* beta = (const float*)d_in[1];
    const float* fu   = (const float*)d_in[2];
    const float* fv   = (const float*)d_in[3];
    float* out = (float*)d_out;

    fill_tw_kernel<<<2, 256>>>();
    smooth3_kernel<<<dim3(1024, 16), 256>>>(fu, fv);
    finalize_kernel<<<16, 256>>>();
    update_kernel<<<BHW / 4 / 256, 256>>>(x, beta);
    fft_fwd_div_kernel<<<1024, 128>>>();
    fft_col_poisson_kernel<<<NB * 129, 256>>>();
    fft_inv_real_kernel<<<NB * 512, 256>>>();
    final_kernel<<<BHW / 4 / 256, 256>>>(x, out);
}

// round 17
// speedup vs baseline: 1.1863x; 1.0287x over previous
#include <cuda_runtime.h>
#include <math.h>

#define NB 8
#define NH 1024
#define NW 1024
#define HW (1 << 20)
#define BHW (NB * HW)

#define NU 0.01f
#define DT 0.01f

#define PD(i) ((i) + ((i) >> 5))

#define C1ROW 520
#define C1BATCH (1024 * C1ROW)

// ------------------------- device scratch -------------------------
__device__ float  g_fa[2 * BHW];
__device__ float  g_unew[BHW];
__device__ float  g_vnew[BHW];
__device__ float2 g_c1[NB * C1BATCH];
__device__ float  g_pcorr[BHW];
__device__ float  g_partials[16384];
__device__ float  g_invnorm[16];
__device__ float2 g_tw[512];           // tw[k] = exp(-2*pi*i*k/1024)

// ------------------------- complex helpers -------------------------
__device__ __forceinline__ float2 cmul(float2 a, float2 b) {
    return make_float2(a.x * b.x - a.y * b.y, a.x * b.y + a.y * b.x);
}
__device__ __forceinline__ float2 cadd(float2 a, float2 b) { return make_float2(a.x + b.x, a.y + b.y); }
__device__ __forceinline__ float2 csub(float2 a, float2 b) { return make_float2(a.x - b.x, a.y - b.y); }

__device__ __forceinline__ constexpr int brev5(int v) {
    return ((v & 1) << 4) | ((v & 2) << 2) | (v & 4) | ((v & 8) >> 2) | ((v & 16) >> 4);
}
__device__ __forceinline__ int brev10(int v) { return (int)(__brev((unsigned)v) >> 22); }

__constant__ float2 W32C[16] = {
    { 1.000000000f, -0.000000000f}, { 0.980785280f, -0.195090322f},
    { 0.923879533f, -0.382683432f}, { 0.831469612f, -0.555570233f},
    { 0.707106781f, -0.707106781f}, { 0.555570233f, -0.831469612f},
    { 0.382683432f, -0.923879533f}, { 0.195090322f, -0.980785280f},
    { 0.000000000f, -1.000000000f}, {-0.195090322f, -0.980785280f},
    {-0.382683432f, -0.923879533f}, {-0.555570233f, -0.831469612f},
    {-0.707106781f, -0.707106781f}, {-0.831469612f, -0.555570233f},
    {-0.923879533f, -0.382683432f}, {-0.980785280f, -0.195090322f},
};

__global__ void fill_tw_kernel() {
    int j = blockIdx.x * 256 + threadIdx.x;      // [0,512)
    float sn, cs;
    sincosf(-6.283185307179586f * (float)j * (1.0f / 1024.0f), &sn, &cs);
    g_tw[j] = make_float2(cs, sn);
}

// 32-pt in-place DIF (natural in, X[k] at r[brev5(k)])
__device__ __forceinline__ void dif32(float2* r) {
    #pragma unroll
    for (int t = 0; t < 5; t++) {
        const int h = 16 >> t;
        #pragma unroll
        for (int g = 0; g < (16 / h); g++) {
            #pragma unroll
            for (int q = 0; q < h; q++) {
                int i0 = ((g * h) << 1) + q, i1 = i0 + h;
                float2 A = r[i0], B = r[i1];
                r[i0] = cadd(A, B);
                r[i1] = cmul(csub(A, B), W32C[q << t]);
            }
        }
    }
}

// Warp 1024-pt forward FFT. In: r[n1] = z[32*n1 + lane]. Out: r[j] = Z[32*brev5(j) + lane].
__device__ __forceinline__ void fft1024_warp(float2* r, float2* zb, int lane) {
    dif32(r);
    float sn, cs;
    sincosf((float)lane * -6.135923151542565e-3f, &sn, &cs);
    float2 w1 = make_float2(cs, sn), w = w1;
    #pragma unroll
    for (int k1 = 1; k1 < 32; k1++) {
        r[brev5(k1)] = cmul(r[brev5(k1)], w);
        w = cmul(w, w1);
    }
    __syncwarp();
    #pragma unroll
    for (int k1 = 0; k1 < 32; k1++) zb[lane * 33 + k1] = r[brev5(k1)];
    __syncwarp();
    #pragma unroll
    for (int n2 = 0; n2 < 32; n2++) r[n2] = zb[n2 * 33 + lane];
    dif32(r);
}

// ------------------------- block FFT machinery -------------------------
__device__ __forceinline__ void build_tw(float* twR, float* twI, int tid) {
    #pragma unroll
    for (int k = 0; k < 2; k++) {
        int j = tid + k * 256;
        float2 w = g_tw[j];
        twR[PD(j)] = w.x; twI[PD(j)] = w.y;
    }
}

#define FWD_DOUBLE(sR, sI, twR, twI, bi, t)                                     \
{                                                                               \
    const int h = 512 >> (t), h2 = h >> 1;                                      \
    int q = (bi) & (h2 - 1);                                                    \
    int B = (bi) >> (8 - (t));                                                  \
    int adr = B * (h << 1) + q;                                                 \
    int a0 = PD(adr), a1 = PD(adr + h2), a2 = PD(adr + h), a3 = PD(adr + h + h2); \
    float x0r = sR[a0], x0i = sI[a0], x1r = sR[a1], x1i = sI[a1];               \
    float x2r = sR[a2], x2i = sI[a2], x3r = sR[a3], x3i = sI[a3];               \
    int i0 = PD(q << (t)), i1 = PD(q << ((t) + 1));                             \
    float w0r = twR[i0], w0i = twI[i0];                                         \
    float w1r = twR[i1], w1i = twI[i1];                                         \
    float u0r = x0r + x2r, u0i = x0i + x2i;                                     \
    float d0r = x0r - x2r, d0i = x0i - x2i;                                     \
    float e0r = d0r * w0r - d0i * w0i, e0i = d0r * w0i + d0i * w0r;             \
    float u1r = x1r + x3r, u1i = x1i + x3i;                                     \
    float d1r = x1r - x3r, d1i = x1i - x3i;                                     \
    float e1r = d1r * w0i + d1i * w0r, e1i = -d1r * w0r + d1i * w0i;            \
    sR[a0] = u0r + u1r; sI[a0] = u0i + u1i;                                     \
    float f0r = u0r - u1r, f0i = u0i - u1i;                                     \
    sR[a1] = f0r * w1r - f0i * w1i; sI[a1] = f0r * w1i + f0i * w1r;             \
    sR[a2] = e0r + e1r; sI[a2] = e0i + e1i;                                     \
    float f1r = e0r - e1r, f1i = e0i - e1i;                                     \
    sR[a3] = f1r * w1r - f1i * w1i; sI[a3] = f1r * w1i + f1i * w1r;             \
}

#define INV_DOUBLE(sR, sI, twR, twI, bi, t)                                     \
{                                                                               \
    const int h = 1 << (t);                                                     \
    int q = (bi) & (h - 1);                                                     \
    int B = (bi) >> (t);                                                        \
    int e0 = B * (h << 2) + q;                                                  \
    int a0 = PD(e0), a1 = PD(e0 + h), a2 = PD(e0 + 2 * h), a3 = PD(e0 + 3 * h); \
    float x0r = sR[a0], x0i = sI[a0], x1r = sR[a1], x1i = sI[a1];               \
    float x2r = sR[a2], x2i = sI[a2], x3r = sR[a3], x3i = sI[a3];               \
    int i0 = PD(q << (9 - (t))), i1 = PD(q << (8 - (t)));                       \
    float c0r = twR[i0], c0i = -twI[i0];                                        \
    float c1r = twR[i1], c1i = -twI[i1];                                        \
    float t1r = c0r * x1r - c0i * x1i, t1i = c0r * x1i + c0i * x1r;             \
    float b0r = x0r + t1r, b0i = x0i + t1i, b1r = x0r - t1r, b1i = x0i - t1i;   \
    float t3r = c0r * x3r - c0i * x3i, t3i = c0r * x3i + c0i * x3r;             \
    float b2r = x2r + t3r, b2i = x2i + t3i, b3r = x2r - t3r, b3i = x2i - t3i;   \
    float t2r = c1r * b2r - c1i * b2i, t2i = c1r * b2i + c1i * b2r;             \
    sR[a0] = b0r + t2r; sI[a0] = b0i + t2i;                                     \
    sR[a2] = b0r - t2r; sI[a2] = b0i - t2i;                                     \
    float gr = -c1i, gi = c1r;                                                  \
    float t4r = gr * b3r - gi * b3i, t4i = gr * b3i + gi * b3r;                 \
    sR[a1] = b1r + t4r; sI[a1] = b1i + t4i;                                     \
    sR[a3] = b1r - t4r; sI[a3] = b1i - t4i;                                     \
}

// ---- radix-16 fused pass: forward DIF stages t..t+3 (t compile-time 0 or 4) ----
__device__ __forceinline__ void fwd_quad(float* cR, float* cI,
                                         const float* twR, const float* twI,
                                         int gi, const int t) {
    const int h = 512 >> t, u = h >> 3;
    int q = gi & (u - 1);
    int B = gi >> (6 - t);
    int base = B * (h << 1) + q;
    float xr[16], xi[16];
    #pragma unroll
    for (int m = 0; m < 16; m++) {
        int a = PD(base + m * u);
        xr[m] = cR[a]; xi[m] = cI[a];
    }
    #pragma unroll
    for (int m = 0; m < 8; m++) {
        int iw = PD((q + m * u) << t);
        float wr = twR[iw], wi = twI[iw];
        float ar = xr[m], ai = xi[m], br = xr[m + 8], bi = xi[m + 8];
        xr[m] = ar + br; xi[m] = ai + bi;
        float dr = ar - br, di = ai - bi;
        xr[m + 8] = dr * wr - di * wi; xi[m + 8] = dr * wi + di * wr;
    }
    #pragma unroll
    for (int g = 0; g < 16; g += 8) {
        #pragma unroll
        for (int m2 = 0; m2 < 4; m2++) {
            int i0 = g + m2, i1 = i0 + 4;
            int iw = PD((q + m2 * u) << (t + 1));
            float wr = twR[iw], wi = twI[iw];
            float ar = xr[i0], ai = xi[i0], br = xr[i1], bi = xi[i1];
            xr[i0] = ar + br; xi[i0] = ai + bi;
            float dr = ar - br, di = ai - bi;
            xr[i1] = dr * wr - di * wi; xi[i1] = dr * wi + di * wr;
        }
    }
    #pragma unroll
    for (int g = 0; g < 16; g += 4) {
        #pragma unroll
        for (int m2 = 0; m2 < 2; m2++) {
            int i0 = g + m2, i1 = i0 + 2;
            int iw = PD((q + m2 * u) << (t + 2));
            float wr = twR[iw], wi = twI[iw];
            float ar = xr[i0], ai = xi[i0], br = xr[i1], bi = xi[i1];
            xr[i0] = ar + br; xi[i0] = ai + bi;
            float dr = ar - br, di = ai - bi;
            xr[i1] = dr * wr - di * wi; xi[i1] = dr * wi + di * wr;
        }
    }
    {
        int iw = PD(q << (t + 3));
        float wr = twR[iw], wi = twI[iw];
        #pragma unroll
        for (int g = 0; g < 16; g += 2) {
            float ar = xr[g], ai = xi[g], br = xr[g + 1], bi = xi[g + 1];
            xr[g] = ar + br; xi[g] = ai + bi;
            float dr = ar - br, di = ai - bi;
            xr[g + 1] = dr * wr - di * wi; xi[g + 1] = dr * wi + di * wr;
        }
    }
    #pragma unroll
    for (int m = 0; m < 16; m++) {
        int a = PD(base + m * u);
        cR[a] = xr[m]; cI[a] = xi[m];
    }
}

// ---- radix-16 fused pass: inverse DIT stages t..t+3 (conj twiddles), t in {0,4} ----
__device__ __forceinline__ void inv_quad(float* cR, float* cI,
                                         const float* twR, const float* twI,
                                         int gi, const int t) {
    const int h = 1 << t;
    int q = gi & (h - 1);
    int B = gi >> t;
    int base = B * (h << 4) + q;
    float xr[16], xi[16];
    #pragma unroll
    for (int m = 0; m < 16; m++) {
        int a = PD(base + m * h);
        xr[m] = cR[a]; xi[m] = cI[a];
    }
    {
        int iw = PD(q << (9 - t));
        float wr = twR[iw], wi = -twI[iw];
        #pragma unroll
        for (int g = 0; g < 16; g += 2) {
            float br = xr[g + 1], bi = xi[g + 1];
            float tr = wr * br - wi * bi, ti = wr * bi + wi * br;
            float ar = xr[g], ai = xi[g];
            xr[g] = ar + tr; xi[g] = ai + ti;
            xr[g + 1] = ar - tr; xi[g + 1] = ai - ti;
        }
    }
    #pragma unroll
    for (int g = 0; g < 16; g += 4) {
        #pragma unroll
        for (int m2 = 0; m2 < 2; m2++) {
            int i0 = g + m2, i1 = i0 + 2;
            int iw = PD((q + m2 * h) << (8 - t));
            float wr = twR[iw], wi = -twI[iw];
            float br = xr[i1], bi = xi[i1];
            float tr = wr * br - wi * bi, ti = wr * bi + wi * br;
            float ar = xr[i0], ai = xi[i0];
            xr[i0] = ar + tr; xi[i0] = ai + ti;
            xr[i1] = ar - tr; xi[i1] = ai - ti;
        }
    }
    #pragma unroll
    for (int g = 0; g < 16; g += 8) {
        #pragma unroll
        for (int m2 = 0; m2 < 4; m2++) {
            int i0 = g + m2, i1 = i0 + 4;
            int iw = PD((q + m2 * h) << (7 - t));
            float wr = twR[iw], wi = -twI[iw];
            float br = xr[i1], bi = xi[i1];
            float tr = wr * br - wi * bi, ti = wr * bi + wi * br;
            float ar = xr[i0], ai = xi[i0];
            xr[i0] = ar + tr; xi[i0] = ai + ti;
            xr[i1] = ar - tr; xi[i1] = ai - ti;
        }
    }
    #pragma unroll
    for (int m2 = 0; m2 < 8; m2++) {
        int iw = PD((q + m2 * h) << (6 - t));
        float wr = twR[iw], wi = -twI[iw];
        float br = xr[m2 + 8], bi = xi[m2 + 8];
        float tr = wr * br - wi * bi, ti = wr * bi + wi * br;
        float ar = xr[m2], ai = xi[m2];
        xr[m2] = ar + tr; xi[m2] = ai + ti;
        xr[m2 + 8] = ar - tr; xi[m2 + 8] = ai - ti;
    }
    #pragma unroll
    for (int m = 0; m < 16; m++) {
        int a = PD(base + m * h);
        cR[a] = xr[m]; cI[a] = xi[m];
    }
}

// ------------------------- block reduce -------------------------
__device__ __forceinline__ float block_reduce_256(float v, float* red) {
    #pragma unroll
    for (int o = 16; o > 0; o >>= 1) v += __shfl_down_sync(0xffffffffu, v, o);
    int lane = threadIdx.x & 31, wid = threadIdx.x >> 5;
    if (lane == 0) red[wid] = v;
    __syncthreads();
    float s = 0.0f;
    if (wid == 0) {
        s = (lane < 8) ? red[lane] : 0.0f;
        #pragma unroll
        for (int o = 4; o > 0; o >>= 1) s += __shfl_down_sync(0xffffffffu, s, o);
    }
    return s;
}

// ------------------------- fused 3x smoothing + norm partials -------------------------
__global__ void smooth3_kernel(const float* __restrict__ su_ext,
                               const float* __restrict__ sv_ext) {
    __shared__ float t0[38][40];
    __shared__ float t1[38][40];
    __shared__ float red[8];
    int slab = blockIdx.y;
    int fb = slab >> 3, b = slab & 7;
    const float* src = (fb ? sv_ext : su_ext) + (b << 20);
    int tile = blockIdx.x;
    int ty0 = (tile >> 5) << 5;
    int tx0 = (tile & 31) << 5;
    int tid = threadIdx.x;

    for (int i = tid; i < 38 * 38; i += 256) {
        int ly = i / 38, lx = i - ly * 38;
        int gy = (ty0 + ly - 3) & 1023;
        int gx = (tx0 + lx - 3) & 1023;
        t0[ly][lx] = src[(gy << 10) + gx];
    }
    __syncthreads();
    for (int i = tid; i < 36 * 36; i += 256) {
        int ly = i / 36, lx = i - ly * 36;
        ly += 1; lx += 1;
        float c = t0[ly][lx];
        t1[ly][lx] = c + 0.1f * (t0[ly][lx-1] + t0[ly][lx+1] + t0[ly-1][lx] + t0[ly+1][lx] - 4.0f * c);
    }
    __syncthreads();
    for (int i = tid; i < 34 * 34; i += 256) {
        int ly = i / 34, lx = i - ly * 34;
        ly += 2; lx += 2;
        float c = t1[ly][lx];
        t0[ly][lx] = c + 0.1f * (t1[ly][lx-1] + t1[ly][lx+1] + t1[ly-1][lx] + t1[ly+1][lx] - 4.0f * c);
    }
    __syncthreads();
    float ss = 0.0f;
    float* dst = g_fa + fb * BHW + (b << 20);
    for (int i = tid; i < 1024; i += 256) {
        int ly = (i >> 5) + 3, lx = (i & 31) + 3;
        float c = t0[ly][lx];
        float o = c + 0.1f * (t0[ly][lx-1] + t0[ly][lx+1] + t0[ly-1][lx] + t0[ly+1][lx] - 4.0f * c);
        dst[((ty0 + ly - 3) << 10) + (tx0 + lx - 3)] = o;
        ss += o * o;
    }
    float tot = block_reduce_256(ss, red);
    if (tid == 0) g_partials[slab * 1024 + tile] = tot;
}

__global__ void finalize_kernel() {
    int r = blockIdx.x;
    float s = 0.0f;
    for (int i = threadIdx.x; i < 1024; i += 256) s += g_partials[r * 1024 + i];
    __shared__ float red[8];
    float tot = block_reduce_256(s, red);
    if (threadIdx.x == 0) {
        float nrm = sqrtf(tot);
        g_invnorm[r] = 1.0f / fmaxf(nrm, 1e-12f);
    }
}

// ------------------------- main update (float4 vectorized) -------------------------
__global__ void update_kernel(const float* __restrict__ xin,
                              const float* __restrict__ beta) {
    int gid = blockIdx.x * 256 + threadIdx.x;          // over BHW/4
    int b  = gid >> 18;
    int t  = gid & 0x3FFFF;
    int y  = t >> 8;
    int x4 = (t & 255) << 2;
    int row = y << 10;
    int rp = ((y + 1) & 1023) << 10;
    int rm = ((y - 1) & 1023) << 10;
    int xm = (x4 - 1) & 1023, xp = (x4 + 4) & 1023;

    const float* u = xin + (size_t)(b * 3 + 0) * HW;
    const float* v = xin + (size_t)(b * 3 + 1) * HW;
    const float* p = xin + (size_t)(b * 3 + 2) * HW;

    float4 uc4  = *(const float4*)(u + row + x4);
    float4 uyp4 = *(const float4*)(u + rp + x4);
    float4 uym4 = *(const float4*)(u + rm + x4);
    float  uml  = u[row + xm], upr = u[row + xp];

    float4 vc4  = *(const float4*)(v + row + x4);
    float4 vyp4 = *(const float4*)(v + rp + x4);
    float4 vym4 = *(const float4*)(v + rm + x4);
    float  vml  = v[row + xm], vpr = v[row + xp];

    float4 pc4  = *(const float4*)(p + row + x4);
    float4 pyp4 = *(const float4*)(p + rp + x4);
    float4 pym4 = *(const float4*)(p + rm + x4);
    float  pml  = p[row + xm], ppr = p[row + xp];

    float4 fu4 = *(const float4*)(g_fa + (b << 20) + row + x4);
    float4 fv4 = *(const float4*)(g_fa + BHW + (b << 20) + row + x4);

    float sb = sqrtf(beta[b]);
    float inu = g_invnorm[b], inv_ = g_invnorm[8 + b];

    float uu[6] = {uml, uc4.x, uc4.y, uc4.z, uc4.w, upr};
    float vv[6] = {vml, vc4.x, vc4.y, vc4.z, vc4.w, vpr};
    float pp[6] = {pml, pc4.x, pc4.y, pc4.z, pc4.w, ppr};
    float uypA[4] = {uyp4.x, uyp4.y, uyp4.z, uyp4.w};
    float uymA[4] = {uym4.x, uym4.y, uym4.z, uym4.w};
    float vypA[4] = {vyp4.x, vyp4.y, vyp4.z, vyp4.w};
    float vymA[4] = {vym4.x, vym4.y, vym4.z, vym4.w};
    float pypA[4] = {pyp4.x, pyp4.y, pyp4.z, pyp4.w};
    float pymA[4] = {pym4.x, pym4.y, pym4.z, pym4.w};
    float fuA[4]  = {fu4.x, fu4.y, fu4.z, fu4.w};
    float fvA[4]  = {fv4.x, fv4.y, fv4.z, fv4.w};

    float uo[4], vo[4];
    #pragma unroll
    for (int i = 0; i < 4; i++) {
        float uc = uu[i + 1], vc = vv[i + 1];
        float adv_u = uc * 0.5f * (uu[i + 2] - uu[i]) + vc * 0.5f * (uypA[i] - uymA[i]);
        float adv_v = uc * 0.5f * (vv[i + 2] - vv[i]) + vc * 0.5f * (vypA[i] - vymA[i]);
        float lap_u = uu[i + 2] + uu[i] + uypA[i] + uymA[i] - 4.0f * uc;
        float lap_v = vv[i + 2] + vv[i] + vypA[i] + vymA[i] - 4.0f * vc;
        float dpdx = 0.5f * (pp[i + 2] - pp[i]);
        float dpdy = 0.5f * (pypA[i] - pymA[i]);
        uo[i] = uc + DT * (-adv_u + NU * lap_u - dpdx) + sb * (fuA[i] * inu);
        vo[i] = vc + DT * (-adv_v + NU * lap_v - dpdy) + sb * (fvA[i] * inv_);
    }
    *(float4*)(g_unew + (b << 20) + row + x4) = make_float4(uo[0], uo[1], uo[2], uo[3]);
    *(float4*)(g_vnew + (b << 20) + row + x4) = make_float4(vo[0], vo[1], vo[2], vo[3]);
}

// ------------------------- fwd FFT over x: one warp per packed row pair -------------------------
__global__ void __launch_bounds__(128) fft_fwd_div_kernel() {
    __shared__ float2 pool[4 * 1056];
    int tid = threadIdx.x, wid = tid >> 5, lane = tid & 31;
    int pairId = blockIdx.x * 4 + wid;       // b*512 + yp
    int b = pairId >> 9, yp = pairId & 511;
    int y0 = yp << 1, y1 = y0 + 1;
    int ub = b << 20;
    int r0 = y0 << 10, r1 = y1 << 10;
    int ym0 = ((y0 - 1) & 1023) << 10;
    int yp1 = ((y1 + 1) & 1023) << 10;

    float2 r[32];
    #pragma unroll
    for (int n1 = 0; n1 < 32; n1++) {
        int x = (n1 << 5) + lane;
        int xp = (x + 1) & 1023, xm = (x - 1) & 1023;
        float d0 = 0.5f * (g_unew[ub + r0 + xp] - g_unew[ub + r0 + xm])
                 + 0.5f * (g_vnew[ub + r1 + x]  - g_vnew[ub + ym0 + x]);
        float d1 = 0.5f * (g_unew[ub + r1 + xp] - g_unew[ub + r1 + xm])
                 + 0.5f * (g_vnew[ub + yp1 + x] - g_vnew[ub + r0 + x]);
        r[n1] = make_float2(d0, d1);
    }

    float2* zb = pool + wid * 1056;
    fft1024_warp(r, zb, lane);

    __syncwarp();
    #pragma unroll
    for (int k2 = 0; k2 < 32; k2++) zb[k2 * 33 + lane] = r[brev5(k2)];
    __syncwarp();

    float2* c0 = g_c1 + b * C1BATCH + y0 * C1ROW;
    float2* c1 = g_c1 + b * C1BATCH + y1 * C1ROW;
    #pragma unroll
    for (int m = 0; m < 17; m++) {
        int k = lane + (m << 5);
        if (k <= 512) {
            int km = (1024 - k) & 1023;
            float2 A = zb[(k >> 5) * 33 + (k & 31)];
            float2 B = zb[(km >> 5) * 33 + (km & 31)];
            c0[k] = make_float2(0.5f * (A.x + B.x), 0.5f * (A.y - B.y));
            c1[k] = make_float2(0.5f * (A.y + B.y), 0.5f * (B.x - A.x));
        }
    }
}

// ------------------------- fused column pipeline (radix-16 passes) -------------------------
#define CS 1057
__global__ void __launch_bounds__(256, 2) fft_col_poisson_kernel() {
    __shared__ float sR[4 * CS], sI[4 * CS];
    __shared__ float twR[528], twI[528];

    int blk = blockIdx.x;                    // b*129 + g
    int b = blk / 129, g = blk - b * 129;
    int col0 = g << 2;
    int tid = threadIdx.x;                   // 256
    float2* base = g_c1 + b * C1BATCH;

    build_tw(twR, twI, tid);

    int c = tid & 3, yy = tid >> 2;
    int col = col0 + c;
    #pragma unroll
    for (int m = 0; m < 16; m++) {
        int y = yy + (m << 6);
        float2 v = base[y * C1ROW + col];
        sR[c * CS + PD(y)] = v.x; sI[c * CS + PD(y)] = v.y;
    }
    __syncthreads();

    int cc = tid >> 6, r = tid & 63;
    float* cR = sR + cc * CS;
    float* cI = sI + cc * CS;

    fwd_quad(cR, cI, twR, twI, r, 0);
    __syncthreads();
    fwd_quad(cR, cI, twR, twI, r, 4);
    __syncthreads();
    #pragma unroll
    for (int k = 0; k < 4; k++) {
        int bi = r + (k << 6);
        FWD_DOUBLE(cR, cI, twR, twI, bi, 8);
    }
    __syncthreads();

    float tkx = (float)min(col, 512);
    #pragma unroll
    for (int m = 0; m < 16; m++) {
        int ry = yy + (m << 6);
        int ky = brev10(ry);
        float tky = (float)min(ky, 1024 - ky);
        float k2 = tkx * tkx + tky * tky;
        float mm = (col == 0 && ky == 0) ? 0.0f
                 : (-1.0f / (39.47841760435743f * k2)) * (1.0f / 1024.0f);
        int a = c * CS + PD(ry);
        sR[a] *= mm; sI[a] *= mm;
    }
    __syncthreads();

    inv_quad(cR, cI, twR, twI, r, 0);
    __syncthreads();
    inv_quad(cR, cI, twR, twI, r, 4);
    __syncthreads();
    #pragma unroll
    for (int k = 0; k < 4; k++) {
        int bi = r + (k << 6);
        INV_DOUBLE(cR, cI, twR, twI, bi, 8);
    }
    __syncthreads();

    #pragma unroll
    for (int m = 0; m < 16; m++) {
        int y = yy + (m << 6);
        base[y * C1ROW + col] = make_float2(sR[c * CS + PD(y)], sI[c * CS + PD(y)]);
    }
}

// ------------------------- inverse FFT over x: 4 row pairs per block, radix-16 passes -------------------------
#define CS2 1058
__global__ void __launch_bounds__(256, 2) fft_inv_real_kernel() {
    __shared__ float sR[4 * CS2], sI[4 * CS2];
    __shared__ float twR[528], twI[528];

    int tid = threadIdx.x;
    build_tw(twR, twI, tid);

    int p = tid >> 6, idx = tid & 63;
    int pairId = blockIdx.x * 4 + p;         // b*512 + yp
    int b = pairId >> 9, yp = pairId & 511;
    int y0 = yp << 1, y1 = y0 + 1;
    const float2* c0 = g_c1 + b * C1BATCH + y0 * C1ROW;
    const float2* c1 = g_c1 + b * C1BATCH + y1 * C1ROW;

    float* aR = sR + p * CS2;                // a1 at PD(k), a2 at 529+PD(k); 529+528=1057<CS2
    float* aI = sI + p * CS2;

    #pragma unroll
    for (int m = 0; m < 9; m++) {
        int k = idx + (m << 6);
        if (k <= 512) {
            float2 v1 = c0[k], v2 = c1[k];
            int a = PD(k);
            aR[a] = v1.x; aI[a] = v1.y;
            aR[529 + a] = v2.x; aI[529 + a] = v2.y;
        }
    }
    __syncthreads();

    // pack B = S1 + i*S2 into registers at storage positions j (spectral k = brev(j))
    float xr[16], xi[16];
    #pragma unroll
    for (int m = 0; m < 16; m++) {
        int j = idx + (m << 6);
        int kk = brev10(j);
        if (kk <= 512) {
            int a = PD(kk);
            xr[m] = aR[a] - aI[529 + a];
            xi[m] = aI[a] + aR[529 + a];
        } else {
            int a = PD(1024 - kk);
            xr[m] = aR[a] + aI[529 + a];
            xi[m] = -aI[a] + aR[529 + a];
        }
    }
    __syncthreads();
    #pragma unroll
    for (int m = 0; m < 16; m++) {
        int j = idx + (m << 6);
        aR[PD(j)] = xr[m]; aI[PD(j)] = xi[m];
    }
    __syncthreads();

    inv_quad(aR, aI, twR, twI, idx, 0);
    __syncthreads();
    inv_quad(aR, aI, twR, twI, idx, 4);
    __syncthreads();
    #pragma unroll
    for (int k = 0; k < 4; k++) {
        int bi = idx + (k << 6);
        INV_DOUBLE(aR, aI, twR, twI, bi, 8);
    }
    __syncthreads();

    const float sc = 1.0f / 1024.0f;
    int bb = b << 20;
    #pragma unroll
    for (int m = 0; m < 16; m++) {
        int x = idx + (m << 6);
        g_pcorr[bb + (y0 << 10) + x] = aR[PD(x)] * sc;
        g_pcorr[bb + (y1 << 10) + x] = aI[PD(x)] * sc;
    }
}

// ------------------------- final (float4 vectorized): subtract grad(p_corr), stack output -------------------------
__global__ void final_kernel(const float* __restrict__ xin, float* __restrict__ out) {
    int gid = blockIdx.x * 256 + threadIdx.x;          // over BHW/4
    int b  = gid >> 18;
    int t  = gid & 0x3FFFF;
    int y  = t >> 8;
    int x4 = (t & 255) << 2;
    int row = y << 10;
    int rp = ((y + 1) & 1023) << 10;
    int rm = ((y - 1) & 1023) << 10;
    int xm = (x4 - 1) & 1023, xp = (x4 + 4) & 1023;
    int bb = b << 20;

    const float* pc = g_pcorr + bb;
    float4 pcc4 = *(const float4*)(pc + row + x4);
    float4 pyp4 = *(const float4*)(pc + rp + x4);
    float4 pym4 = *(const float4*)(pc + rm + x4);
    float  pml  = pc[row + xm], ppr = pc[row + xp];

    float4 un4 = *(const float4*)(g_unew + bb + row + x4);
    float4 vn4 = *(const float4*)(g_vnew + bb + row + x4);
    float4 pin4 = *(const float4*)(xin + (size_t)(b * 3 + 2) * HW + row + x4);

    float ppx[6] = {pml, pcc4.x, pcc4.y, pcc4.z, pcc4.w, ppr};
    float pypA[4] = {pyp4.x, pyp4.y, pyp4.z, pyp4.w};
    float pymA[4] = {pym4.x, pym4.y, pym4.z, pym4.w};
    float unA[4] = {un4.x, un4.y, un4.z, un4.w};
    float vnA[4] = {vn4.x, vn4.y, vn4.z, vn4.w};
    float pinA[4] = {pin4.x, pin4.y, pin4.z, pin4.w};

    float uo[4], vo[4], po[4];
    #pragma unroll
    for (int i = 0; i < 4; i++) {
        uo[i] = unA[i] - 0.5f * (ppx[i + 2] - ppx[i]);
        vo[i] = vnA[i] - 0.5f * (pypA[i] - pymA[i]);
        po[i] = pinA[i] + ppx[i + 1];
    }
    *(float4*)(out + (size_t)(b * 3 + 0) * HW + row + x4) = make_float4(uo[0], uo[1], uo[2], uo[3]);
    *(float4*)(out + (size_t)(b * 3 + 1) * HW + row + x4) = make_float4(vo[0], vo[1], vo[2], vo[3]);
    *(float4*)(out + (size_t)(b * 3 + 2) * HW + row + x4) = make_float4(po[0], po[1], po[2], po[3]);
}

// ------------------------- launch -------------------------
extern "C" void kernel_launch(void* const* d_in, const int* in_sizes, int n_in,
                              void* d_out, int out_size) {
    (void)in_sizes; (void)n_in; (void)out_size;
    const float* x    = (const float*)d_in[0];
    const float* beta = (const float*)d_in[1];
    const float* fu   = (const float*)d_in[2];
    const float* fv   = (const float*)d_in[3];
    float* out = (float*)d_out;

    fill_tw_kernel<<<2, 256>>>();
    smooth3_kernel<<<dim3(1024, 16), 256>>>(fu, fv);
    finalize_kernel<<<16, 256>>>();
    update_kernel<<<BHW / 4 / 256, 256>>>(x, beta);
    fft_fwd_div_kernel<<<1024, 128>>>();
    fft_col_poisson_kernel<<<NB * 129, 256>>>();
    fft_inv_real_kernel<<<NB * 128, 256>>>();
    final_kernel<<<BHW / 4 / 256, 256>>>(x, out);
}